// round 1
// baseline (speedup 1.0000x reference)
#include <cuda_runtime.h>
#include <math.h>
#include <stdint.h>

// Problem constants
#define BB 2
#define LL 2048
#define DD 1024
#define HH 16
#define KK 64
#define ROT 32
#define MROWS (BB * LL)   // 4096

// Scratch (static device arrays: allocation-free)
__device__ float g_q[MROWS * DD];
__device__ float g_k[MROWS * DD];
__device__ float g_v[MROWS * DD];
__device__ float g_ctx[MROWS * DD];

// ---------------------------------------------------------------------------
// SGEMM: C[M,N] = A[M,Kd] * B[Kd,N], all row-major, M%128==0, N%128==0, Kd%8==0
// 128x128 block, 256 threads, 8x8 microtile
// ---------------------------------------------------------------------------
__global__ __launch_bounds__(256) void sgemm128(
    const float* __restrict__ A, const float* __restrict__ B,
    float* __restrict__ C, int M, int N, int Kd) {
  __shared__ float As[8][128];
  __shared__ float Bs[8][128];
  const int tid = threadIdx.x;
  const int crow = blockIdx.y * 128;
  const int ccol = blockIdx.x * 128;

  const int aRow = tid >> 1;           // 0..127
  const int aCol = (tid & 1) << 2;     // 0 or 4
  const int bRow = tid >> 5;           // 0..7
  const int bCol = (tid & 31) << 2;    // 0..124

  const float* Aptr = A + (size_t)(crow + aRow) * Kd + aCol;
  const float* Bptr = B + (size_t)bRow * N + ccol + bCol;

  const int tr = (tid >> 4) << 3;      // row offset of microtile
  const int tc = (tid & 15) << 3;      // col offset of microtile

  float acc[8][8];
  #pragma unroll
  for (int i = 0; i < 8; i++)
    #pragma unroll
    for (int j = 0; j < 8; j++) acc[i][j] = 0.0f;

  for (int k0 = 0; k0 < Kd; k0 += 8) {
    float4 a4 = *(const float4*)Aptr;
    As[aCol + 0][aRow] = a4.x;
    As[aCol + 1][aRow] = a4.y;
    As[aCol + 2][aRow] = a4.z;
    As[aCol + 3][aRow] = a4.w;
    *(float4*)&Bs[bRow][bCol] = *(const float4*)Bptr;
    __syncthreads();
    Aptr += 8;
    Bptr += (size_t)8 * N;

    #pragma unroll
    for (int kk = 0; kk < 8; kk++) {
      float ar[8], br[8];
      *(float4*)&ar[0] = *(float4*)&As[kk][tr];
      *(float4*)&ar[4] = *(float4*)&As[kk][tr + 4];
      *(float4*)&br[0] = *(float4*)&Bs[kk][tc];
      *(float4*)&br[4] = *(float4*)&Bs[kk][tc + 4];
      #pragma unroll
      for (int i = 0; i < 8; i++)
        #pragma unroll
        for (int j = 0; j < 8; j++)
          acc[i][j] += ar[i] * br[j];
    }
    __syncthreads();
  }

  #pragma unroll
  for (int i = 0; i < 8; i++) {
    float* crow_ptr = C + (size_t)(crow + tr + i) * N + ccol + tc;
    *(float4*)(crow_ptr + 0) = make_float4(acc[i][0], acc[i][1], acc[i][2], acc[i][3]);
    *(float4*)(crow_ptr + 4) = make_float4(acc[i][4], acc[i][5], acc[i][6], acc[i][7]);
  }
}

// ---------------------------------------------------------------------------
// RoPE applied in-place to q and k (first ROT dims of each head)
// Interleaved-pair rotation, per-element frequency:
//   out[2i]   = t[2i]*cos(f[2i])   - t[2i+1]*sin(f[2i])
//   out[2i+1] = t[2i+1]*cos(f[2i+1]) + t[2i]*sin(f[2i+1])
// ---------------------------------------------------------------------------
__global__ void rope_kernel(float* __restrict__ q, float* __restrict__ k,
                            const float* __restrict__ rot) {
  int idx = blockIdx.x * 256 + threadIdx.x;   // over MROWS*HH*(ROT/2)
  const int total = MROWS * HH * (ROT / 2);
  if (idx >= total) return;
  int i = idx & 15;              // pair index 0..15
  int h = (idx >> 4) & 15;
  int row = idx >> 8;            // 0..4095
  int l = row & (LL - 1);

  float f0 = rot[l * ROT + 2 * i];
  float f1 = rot[l * ROT + 2 * i + 1];
  float s0, c0, s1, c1;
  sincosf(f0, &s0, &c0);
  sincosf(f1, &s1, &c1);

  int base = row * DD + h * KK + 2 * i;
  float2 tq = *(float2*)&q[base];
  float2 tk = *(float2*)&k[base];
  float2 oq, ok;
  oq.x = tq.x * c0 - tq.y * s0;
  oq.y = tq.y * c1 + tq.x * s1;
  ok.x = tk.x * c0 - tk.y * s0;
  ok.y = tk.y * c1 + tk.x * s1;
  *(float2*)&q[base] = oq;
  *(float2*)&k[base] = ok;
}

// ---------------------------------------------------------------------------
// Flash attention, fp32, full (non-causal) softmax.
// Block: one (b, h, 128-row q tile). 256 threads (16x16): each thread owns
// 8 q-rows x 4 cols. KV iterated in 64-token tiles.
// smem: Qs[d][row] 64x128, Ks[d][tok] 64x68, Vs[tok][d] 64x68, Ps[tok][row] 64x132
// ---------------------------------------------------------------------------
#define FA_SMEM_FLOATS (64 * 128 + 64 * 68 + 64 * 68 + 64 * 132)
#define FA_SMEM_BYTES (FA_SMEM_FLOATS * 4)

__global__ __launch_bounds__(256) void flash_attn(
    const float* __restrict__ gq, const float* __restrict__ gk,
    const float* __restrict__ gv, float* __restrict__ gctx) {
  extern __shared__ float sm[];
  float* Qs = sm;                  // [64][128]
  float* Ks = Qs + 64 * 128;       // [64][68]
  float* Vs = Ks + 64 * 68;        // [64][68]
  float* Ps = Vs + 64 * 68;        // [64][132]

  const int tid = threadIdx.x;
  const int qt = blockIdx.x, h = blockIdx.y, b = blockIdx.z;
  const int ty = tid >> 4, tx = tid & 15;
  const int tr = ty << 3;          // q-row offset (8 rows)
  const int tc = tx << 2;          // col offset (4 cols)
  const int qrow0 = b * LL + qt * 128;
  const int hoff = h * KK;

  // Load Q tile transposed: Qs[d][row]
  {
    int r = tid >> 1;
    int d0 = (tid & 1) * 32;
    const float* src = gq + (size_t)(qrow0 + r) * DD + hoff + d0;
    #pragma unroll
    for (int u = 0; u < 8; u++) {
      float4 x = *(const float4*)(src + 4 * u);
      Qs[(d0 + 4 * u + 0) * 128 + r] = x.x;
      Qs[(d0 + 4 * u + 1) * 128 + r] = x.y;
      Qs[(d0 + 4 * u + 2) * 128 + r] = x.z;
      Qs[(d0 + 4 * u + 3) * 128 + r] = x.w;
    }
  }

  float o[8][4];
  float m[8], l[8];
  #pragma unroll
  for (int i = 0; i < 8; i++) {
    m[i] = -1e30f;
    l[i] = 0.0f;
    #pragma unroll
    for (int c = 0; c < 4; c++) o[i][c] = 0.0f;
  }

  for (int t = 0; t < LL / 64; t++) {
    // Load K (transposed) and V (natural) tiles
    {
      int kbase = b * LL + t * 64;
      int tok = tid >> 2;            // 0..63
      int d0 = (tid & 3) * 16;
      const float* ks = gk + (size_t)(kbase + tok) * DD + hoff + d0;
      const float* vs = gv + (size_t)(kbase + tok) * DD + hoff + d0;
      #pragma unroll
      for (int u = 0; u < 4; u++) {
        float4 x = *(const float4*)(ks + 4 * u);
        Ks[(d0 + 4 * u + 0) * 68 + tok] = x.x;
        Ks[(d0 + 4 * u + 1) * 68 + tok] = x.y;
        Ks[(d0 + 4 * u + 2) * 68 + tok] = x.z;
        Ks[(d0 + 4 * u + 3) * 68 + tok] = x.w;
        float4 y = *(const float4*)(vs + 4 * u);
        *(float4*)&Vs[tok * 68 + d0 + 4 * u] = y;
      }
    }
    __syncthreads();   // KV (and, first iter, Q) visible

    // S = Q K^T for this thread's 8x4 patch
    float s[8][4];
    #pragma unroll
    for (int i = 0; i < 8; i++)
      #pragma unroll
      for (int c = 0; c < 4; c++) s[i][c] = 0.0f;

    #pragma unroll 8
    for (int d = 0; d < 64; d++) {
      float4 q0 = *(float4*)&Qs[d * 128 + tr];
      float4 q1 = *(float4*)&Qs[d * 128 + tr + 4];
      float4 kv = *(float4*)&Ks[d * 68 + tc];
      float qr[8] = {q0.x, q0.y, q0.z, q0.w, q1.x, q1.y, q1.z, q1.w};
      float kc[4] = {kv.x, kv.y, kv.z, kv.w};
      #pragma unroll
      for (int i = 0; i < 8; i++)
        #pragma unroll
        for (int c = 0; c < 4; c++) s[i][c] += qr[i] * kc[c];
    }

    // Online softmax update
    const float scale = 0.125f;   // 1/sqrt(64)
    #pragma unroll
    for (int i = 0; i < 8; i++) {
      #pragma unroll
      for (int c = 0; c < 4; c++) s[i][c] *= scale;
      float mt = fmaxf(fmaxf(s[i][0], s[i][1]), fmaxf(s[i][2], s[i][3]));
      #pragma unroll
      for (int off = 1; off < 16; off <<= 1)
        mt = fmaxf(mt, __shfl_xor_sync(0xffffffffu, mt, off));
      float mn = fmaxf(m[i], mt);
      float corr = __expf(m[i] - mn);
      m[i] = mn;
      float ls = 0.0f;
      float p[4];
      #pragma unroll
      for (int c = 0; c < 4; c++) {
        p[c] = __expf(s[i][c] - mn);
        ls += p[c];
      }
      #pragma unroll
      for (int off = 1; off < 16; off <<= 1)
        ls += __shfl_xor_sync(0xffffffffu, ls, off);
      l[i] = l[i] * corr + ls;
      #pragma unroll
      for (int c = 0; c < 4; c++) {
        o[i][c] *= corr;
        Ps[(tc + c) * 132 + tr + i] = p[c];   // Ps[kv][row]
      }
    }
    __syncthreads();   // Ps visible

    // O += P @ V
    #pragma unroll 8
    for (int j = 0; j < 64; j++) {
      float4 p0 = *(float4*)&Ps[j * 132 + tr];
      float4 p1 = *(float4*)&Ps[j * 132 + tr + 4];
      float4 vv = *(float4*)&Vs[j * 68 + tc];
      float pr[8] = {p0.x, p0.y, p0.z, p0.w, p1.x, p1.y, p1.z, p1.w};
      float vc[4] = {vv.x, vv.y, vv.z, vv.w};
      #pragma unroll
      for (int i = 0; i < 8; i++)
        #pragma unroll
        for (int c = 0; c < 4; c++) o[i][c] += pr[i] * vc[c];
    }
    __syncthreads();   // PV reads done before next tile overwrites
  }

  // Normalize and store ctx[row][h*64 + col]
  #pragma unroll
  for (int i = 0; i < 8; i++) {
    float inv = 1.0f / l[i];
    float4 w = make_float4(o[i][0] * inv, o[i][1] * inv, o[i][2] * inv, o[i][3] * inv);
    *(float4*)&gctx[(size_t)(qrow0 + tr + i) * DD + hoff + tc] = w;
  }
}

// ---------------------------------------------------------------------------
extern "C" void kernel_launch(void* const* d_in, const int* in_sizes, int n_in,
                              void* d_out, int out_size) {
  const float* query    = (const float*)d_in[0];
  const float* key      = (const float*)d_in[1];
  const float* value    = (const float*)d_in[2];
  const float* rot      = (const float*)d_in[3];
  const float* q_kernel = (const float*)d_in[4];
  const float* k_kernel = (const float*)d_in[5];
  const float* v_kernel = (const float*)d_in[6];
  const float* o_kernel = (const float*)d_in[7];
  float* out = (float*)d_out;

  float *pq, *pk, *pv, *pctx;
  cudaGetSymbolAddress((void**)&pq, g_q);
  cudaGetSymbolAddress((void**)&pk, g_k);
  cudaGetSymbolAddress((void**)&pv, g_v);
  cudaGetSymbolAddress((void**)&pctx, g_ctx);

  dim3 gemm_grid(DD / 128, MROWS / 128);   // (8, 32)

  // QKV projections
  sgemm128<<<gemm_grid, 256>>>(query, q_kernel, pq, MROWS, DD, DD);
  sgemm128<<<gemm_grid, 256>>>(key,   k_kernel, pk, MROWS, DD, DD);
  sgemm128<<<gemm_grid, 256>>>(value, v_kernel, pv, MROWS, DD, DD);

  // RoPE on q, k
  {
    int total = MROWS * HH * (ROT / 2);
    rope_kernel<<<(total + 255) / 256, 256>>>(pq, pk, rot);
  }

  // Flash attention
  cudaFuncSetAttribute(flash_attn, cudaFuncAttributeMaxDynamicSharedMemorySize,
                       FA_SMEM_BYTES);
  flash_attn<<<dim3(LL / 128, HH, BB), 256, FA_SMEM_BYTES>>>(pq, pk, pv, pctx);

  // Output projection
  sgemm128<<<gemm_grid, 256>>>(pctx, o_kernel, out, MROWS, DD, DD);
}

// round 2
// speedup vs baseline: 1.3617x; 1.3617x over previous
#include <cuda_runtime.h>
#include <math.h>
#include <stdint.h>

// Problem constants
#define BB 2
#define LL 2048
#define DD 1024
#define HH 16
#define KK 64
#define ROT 32
#define MROWS (BB * LL)   // 4096

// Scratch (static device arrays: allocation-free)
__device__ float g_q[MROWS * DD];
__device__ float g_k[MROWS * DD];
__device__ float g_v[MROWS * DD];
__device__ float g_ctx[MROWS * DD];

// ---------------------------------------------------------------------------
// TF32 tensor-core GEMM: C[M,N] = A[M,Kd] * B[Kd,N], row-major.
// Block tile 128x128, BK=16. 256 threads = 8 warps (4 m x 2 n), each warp
// computes 32x64 via 2x8 m16n8k8 tf32 mma fragments.
// ---------------------------------------------------------------------------
#define AS_STRIDE 136   // 136 mod 32 == 8 -> conflict-free fragment loads

__device__ __forceinline__ uint32_t f2tf32(float f) {
  uint32_t u;
  asm("cvt.rna.tf32.f32 %0, %1;" : "=r"(u) : "f"(f));
  return u;
}

__device__ __forceinline__ void mma_tf32(float c[4], const uint32_t a[4],
                                         uint32_t b0, uint32_t b1) {
  asm("mma.sync.aligned.m16n8k8.row.col.f32.tf32.tf32.f32 "
      "{%0,%1,%2,%3},{%4,%5,%6,%7},{%8,%9},{%0,%1,%2,%3};"
      : "+f"(c[0]), "+f"(c[1]), "+f"(c[2]), "+f"(c[3])
      : "r"(a[0]), "r"(a[1]), "r"(a[2]), "r"(a[3]), "r"(b0), "r"(b1));
}

__global__ __launch_bounds__(256) void sgemm_tf32(
    const float* __restrict__ A, const float* __restrict__ B,
    float* __restrict__ C, int M, int N, int Kd) {
  __shared__ uint32_t As[16 * AS_STRIDE];   // As[k][m] (transposed)
  __shared__ uint32_t Bs[16 * AS_STRIDE];   // Bs[k][n]

  const int tid = threadIdx.x;
  const int warp = tid >> 5, lane = tid & 31;
  const int g = lane >> 2, tc = lane & 3;
  const int wm = warp & 3, wn = warp >> 2;
  const int m_base = wm * 32;
  const int n_base = wn * 64;
  const int crow = blockIdx.y * 128;
  const int ccol = blockIdx.x * 128;

  // Loader indices
  const int aRow = tid >> 1;          // 0..127
  const int aColH = (tid & 1) * 8;    // 0 or 8
  const int bRow = tid >> 4;          // 0..15
  const int bCol = (tid & 15) * 8;    // 0..120

  const float* Ap = A + (size_t)(crow + aRow) * Kd + aColH;
  const float* Bp = B + (size_t)bRow * N + ccol + bCol;

  float acc[2][8][4];
  #pragma unroll
  for (int mi = 0; mi < 2; mi++)
    #pragma unroll
    for (int ni = 0; ni < 8; ni++)
      #pragma unroll
      for (int r = 0; r < 4; r++) acc[mi][ni][r] = 0.0f;

  for (int k0 = 0; k0 < Kd; k0 += 16) {
    // A tile -> As[k][m] (transposed), tf32-converted
    {
      float4 x = *(const float4*)Ap;
      float4 y = *(const float4*)(Ap + 4);
      As[(aColH + 0) * AS_STRIDE + aRow] = f2tf32(x.x);
      As[(aColH + 1) * AS_STRIDE + aRow] = f2tf32(x.y);
      As[(aColH + 2) * AS_STRIDE + aRow] = f2tf32(x.z);
      As[(aColH + 3) * AS_STRIDE + aRow] = f2tf32(x.w);
      As[(aColH + 4) * AS_STRIDE + aRow] = f2tf32(y.x);
      As[(aColH + 5) * AS_STRIDE + aRow] = f2tf32(y.y);
      As[(aColH + 6) * AS_STRIDE + aRow] = f2tf32(y.z);
      As[(aColH + 7) * AS_STRIDE + aRow] = f2tf32(y.w);
    }
    // B tile -> Bs[k][n], tf32-converted
    {
      float4 x = *(const float4*)Bp;
      float4 y = *(const float4*)(Bp + 4);
      uint32_t* dst = &Bs[bRow * AS_STRIDE + bCol];
      dst[0] = f2tf32(x.x); dst[1] = f2tf32(x.y);
      dst[2] = f2tf32(x.z); dst[3] = f2tf32(x.w);
      dst[4] = f2tf32(y.x); dst[5] = f2tf32(y.y);
      dst[6] = f2tf32(y.z); dst[7] = f2tf32(y.w);
    }
    __syncthreads();
    Ap += 16;
    Bp += (size_t)16 * N;

    #pragma unroll
    for (int ks = 0; ks < 16; ks += 8) {
      // A fragments (2 m-tiles)
      uint32_t afr[2][4];
      #pragma unroll
      for (int mi = 0; mi < 2; mi++) {
        int base = (ks + tc) * AS_STRIDE + m_base + mi * 16 + g;
        afr[mi][0] = As[base];
        afr[mi][1] = As[base + 8];
        afr[mi][2] = As[base + 4 * AS_STRIDE];
        afr[mi][3] = As[base + 4 * AS_STRIDE + 8];
      }
      // B fragments (8 n-tiles)
      uint32_t bfr[8][2];
      #pragma unroll
      for (int ni = 0; ni < 8; ni++) {
        int base = (ks + tc) * AS_STRIDE + n_base + ni * 8 + g;
        bfr[ni][0] = Bs[base];
        bfr[ni][1] = Bs[base + 4 * AS_STRIDE];
      }
      #pragma unroll
      for (int mi = 0; mi < 2; mi++)
        #pragma unroll
        for (int ni = 0; ni < 8; ni++)
          mma_tf32(acc[mi][ni], afr[mi], bfr[ni][0], bfr[ni][1]);
    }
    __syncthreads();
  }

  // Store C
  #pragma unroll
  for (int mi = 0; mi < 2; mi++) {
    #pragma unroll
    for (int ni = 0; ni < 8; ni++) {
      int row = crow + m_base + mi * 16 + g;
      int col = ccol + n_base + ni * 8 + 2 * tc;
      *(float2*)&C[(size_t)row * N + col] =
          make_float2(acc[mi][ni][0], acc[mi][ni][1]);
      *(float2*)&C[(size_t)(row + 8) * N + col] =
          make_float2(acc[mi][ni][2], acc[mi][ni][3]);
    }
  }
}

// ---------------------------------------------------------------------------
// RoPE applied in-place to q and k (first ROT dims of each head)
// ---------------------------------------------------------------------------
__global__ void rope_kernel(float* __restrict__ q, float* __restrict__ k,
                            const float* __restrict__ rot) {
  int idx = blockIdx.x * 256 + threadIdx.x;   // over MROWS*HH*(ROT/2)
  const int total = MROWS * HH * (ROT / 2);
  if (idx >= total) return;
  int i = idx & 15;              // pair index 0..15
  int h = (idx >> 4) & 15;
  int row = idx >> 8;            // 0..4095
  int l = row & (LL - 1);

  float f0 = rot[l * ROT + 2 * i];
  float f1 = rot[l * ROT + 2 * i + 1];
  float s0, c0, s1, c1;
  sincosf(f0, &s0, &c0);
  sincosf(f1, &s1, &c1);

  int base = row * DD + h * KK + 2 * i;
  float2 tq = *(float2*)&q[base];
  float2 tk = *(float2*)&k[base];
  float2 oq, ok;
  oq.x = tq.x * c0 - tq.y * s0;
  oq.y = tq.y * c1 + tq.x * s1;
  ok.x = tk.x * c0 - tk.y * s0;
  ok.y = tk.y * c1 + tk.x * s1;
  *(float2*)&q[base] = oq;
  *(float2*)&k[base] = ok;
}

// ---------------------------------------------------------------------------
// Flash attention, fp32, full (non-causal) softmax. (unchanged from R0)
// ---------------------------------------------------------------------------
#define FA_SMEM_FLOATS (64 * 128 + 64 * 68 + 64 * 68 + 64 * 132)
#define FA_SMEM_BYTES (FA_SMEM_FLOATS * 4)

__global__ __launch_bounds__(256) void flash_attn(
    const float* __restrict__ gq, const float* __restrict__ gk,
    const float* __restrict__ gv, float* __restrict__ gctx) {
  extern __shared__ float sm[];
  float* Qs = sm;                  // [64][128]
  float* Ks = Qs + 64 * 128;       // [64][68]
  float* Vs = Ks + 64 * 68;        // [64][68]
  float* Ps = Vs + 64 * 68;        // [64][132]

  const int tid = threadIdx.x;
  const int qt = blockIdx.x, h = blockIdx.y, b = blockIdx.z;
  const int ty = tid >> 4, tx = tid & 15;
  const int tr = ty << 3;          // q-row offset (8 rows)
  const int tc = tx << 2;          // col offset (4 cols)
  const int qrow0 = b * LL + qt * 128;
  const int hoff = h * KK;

  // Load Q tile transposed: Qs[d][row]
  {
    int r = tid >> 1;
    int d0 = (tid & 1) * 32;
    const float* src = gq + (size_t)(qrow0 + r) * DD + hoff + d0;
    #pragma unroll
    for (int u = 0; u < 8; u++) {
      float4 x = *(const float4*)(src + 4 * u);
      Qs[(d0 + 4 * u + 0) * 128 + r] = x.x;
      Qs[(d0 + 4 * u + 1) * 128 + r] = x.y;
      Qs[(d0 + 4 * u + 2) * 128 + r] = x.z;
      Qs[(d0 + 4 * u + 3) * 128 + r] = x.w;
    }
  }

  float o[8][4];
  float m[8], l[8];
  #pragma unroll
  for (int i = 0; i < 8; i++) {
    m[i] = -1e30f;
    l[i] = 0.0f;
    #pragma unroll
    for (int c = 0; c < 4; c++) o[i][c] = 0.0f;
  }

  for (int t = 0; t < LL / 64; t++) {
    // Load K (transposed) and V (natural) tiles
    {
      int kbase = b * LL + t * 64;
      int tok = tid >> 2;            // 0..63
      int d0 = (tid & 3) * 16;
      const float* ks = gk + (size_t)(kbase + tok) * DD + hoff + d0;
      const float* vs = gv + (size_t)(kbase + tok) * DD + hoff + d0;
      #pragma unroll
      for (int u = 0; u < 4; u++) {
        float4 x = *(const float4*)(ks + 4 * u);
        Ks[(d0 + 4 * u + 0) * 68 + tok] = x.x;
        Ks[(d0 + 4 * u + 1) * 68 + tok] = x.y;
        Ks[(d0 + 4 * u + 2) * 68 + tok] = x.z;
        Ks[(d0 + 4 * u + 3) * 68 + tok] = x.w;
        float4 y = *(const float4*)(vs + 4 * u);
        *(float4*)&Vs[tok * 68 + d0 + 4 * u] = y;
      }
    }
    __syncthreads();   // KV (and, first iter, Q) visible

    // S = Q K^T for this thread's 8x4 patch
    float s[8][4];
    #pragma unroll
    for (int i = 0; i < 8; i++)
      #pragma unroll
      for (int c = 0; c < 4; c++) s[i][c] = 0.0f;

    #pragma unroll 8
    for (int d = 0; d < 64; d++) {
      float4 q0 = *(float4*)&Qs[d * 128 + tr];
      float4 q1 = *(float4*)&Qs[d * 128 + tr + 4];
      float4 kv = *(float4*)&Ks[d * 68 + tc];
      float qr[8] = {q0.x, q0.y, q0.z, q0.w, q1.x, q1.y, q1.z, q1.w};
      float kc[4] = {kv.x, kv.y, kv.z, kv.w};
      #pragma unroll
      for (int i = 0; i < 8; i++)
        #pragma unroll
        for (int c = 0; c < 4; c++) s[i][c] += qr[i] * kc[c];
    }

    // Online softmax update
    const float scale = 0.125f;   // 1/sqrt(64)
    #pragma unroll
    for (int i = 0; i < 8; i++) {
      #pragma unroll
      for (int c = 0; c < 4; c++) s[i][c] *= scale;
      float mt = fmaxf(fmaxf(s[i][0], s[i][1]), fmaxf(s[i][2], s[i][3]));
      #pragma unroll
      for (int off = 1; off < 16; off <<= 1)
        mt = fmaxf(mt, __shfl_xor_sync(0xffffffffu, mt, off));
      float mn = fmaxf(m[i], mt);
      float corr = __expf(m[i] - mn);
      m[i] = mn;
      float ls = 0.0f;
      float p[4];
      #pragma unroll
      for (int c = 0; c < 4; c++) {
        p[c] = __expf(s[i][c] - mn);
        ls += p[c];
      }
      #pragma unroll
      for (int off = 1; off < 16; off <<= 1)
        ls += __shfl_xor_sync(0xffffffffu, ls, off);
      l[i] = l[i] * corr + ls;
      #pragma unroll
      for (int c = 0; c < 4; c++) {
        o[i][c] *= corr;
        Ps[(tc + c) * 132 + tr + i] = p[c];   // Ps[kv][row]
      }
    }
    __syncthreads();   // Ps visible

    // O += P @ V
    #pragma unroll 8
    for (int j = 0; j < 64; j++) {
      float4 p0 = *(float4*)&Ps[j * 132 + tr];
      float4 p1 = *(float4*)&Ps[j * 132 + tr + 4];
      float4 vv = *(float4*)&Vs[j * 68 + tc];
      float pr[8] = {p0.x, p0.y, p0.z, p0.w, p1.x, p1.y, p1.z, p1.w};
      float vc[4] = {vv.x, vv.y, vv.z, vv.w};
      #pragma unroll
      for (int i = 0; i < 8; i++)
        #pragma unroll
        for (int c = 0; c < 4; c++) o[i][c] += pr[i] * vc[c];
    }
    __syncthreads();   // PV reads done before next tile overwrites
  }

  // Normalize and store ctx[row][h*64 + col]
  #pragma unroll
  for (int i = 0; i < 8; i++) {
    float inv = 1.0f / l[i];
    float4 w = make_float4(o[i][0] * inv, o[i][1] * inv, o[i][2] * inv, o[i][3] * inv);
    *(float4*)&gctx[(size_t)(qrow0 + tr + i) * DD + hoff + tc] = w;
  }
}

// ---------------------------------------------------------------------------
extern "C" void kernel_launch(void* const* d_in, const int* in_sizes, int n_in,
                              void* d_out, int out_size) {
  const float* query    = (const float*)d_in[0];
  const float* key      = (const float*)d_in[1];
  const float* value    = (const float*)d_in[2];
  const float* rot      = (const float*)d_in[3];
  const float* q_kernel = (const float*)d_in[4];
  const float* k_kernel = (const float*)d_in[5];
  const float* v_kernel = (const float*)d_in[6];
  const float* o_kernel = (const float*)d_in[7];
  float* out = (float*)d_out;

  float *pq, *pk, *pv, *pctx;
  cudaGetSymbolAddress((void**)&pq, g_q);
  cudaGetSymbolAddress((void**)&pk, g_k);
  cudaGetSymbolAddress((void**)&pv, g_v);
  cudaGetSymbolAddress((void**)&pctx, g_ctx);

  dim3 gemm_grid(DD / 128, MROWS / 128);   // (8, 32)

  // QKV projections (tf32 tensor cores)
  sgemm_tf32<<<gemm_grid, 256>>>(query, q_kernel, pq, MROWS, DD, DD);
  sgemm_tf32<<<gemm_grid, 256>>>(key,   k_kernel, pk, MROWS, DD, DD);
  sgemm_tf32<<<gemm_grid, 256>>>(value, v_kernel, pv, MROWS, DD, DD);

  // RoPE on q, k
  {
    int total = MROWS * HH * (ROT / 2);
    rope_kernel<<<(total + 255) / 256, 256>>>(pq, pk, rot);
  }

  // Flash attention
  cudaFuncSetAttribute(flash_attn, cudaFuncAttributeMaxDynamicSharedMemorySize,
                       FA_SMEM_BYTES);
  flash_attn<<<dim3(LL / 128, HH, BB), 256, FA_SMEM_BYTES>>>(pq, pk, pv, pctx);

  // Output projection (tf32 tensor cores)
  sgemm_tf32<<<gemm_grid, 256>>>(pctx, o_kernel, out, MROWS, DD, DD);
}

// round 5
// speedup vs baseline: 2.3076x; 1.6947x over previous
#include <cuda_runtime.h>
#include <math.h>
#include <stdint.h>

// Problem constants
#define BB 2
#define LL 2048
#define DD 1024
#define HH 16
#define KK 64
#define ROT 32
#define MROWS (BB * LL)   // 4096

// Scratch (static device arrays: allocation-free)
__device__ float g_q[MROWS * DD];
__device__ float g_k[MROWS * DD];
__device__ float g_v[MROWS * DD];
__device__ float g_ctx[MROWS * DD];

__device__ __forceinline__ uint32_t f2tf32(float f) {
  uint32_t u;
  asm("cvt.rna.tf32.f32 %0, %1;" : "=r"(u) : "f"(f));
  return u;
}

__device__ __forceinline__ void mma_tf32(float c[4], const uint32_t a[4],
                                         uint32_t b0, uint32_t b1) {
  asm("mma.sync.aligned.m16n8k8.row.col.f32.tf32.tf32.f32 "
      "{%0,%1,%2,%3},{%4,%5,%6,%7},{%8,%9},{%0,%1,%2,%3};"
      : "+f"(c[0]), "+f"(c[1]), "+f"(c[2]), "+f"(c[3])
      : "r"(a[0]), "r"(a[1]), "r"(a[2]), "r"(a[3]), "r"(b0), "r"(b1));
}

// ---------------------------------------------------------------------------
// TF32 tensor-core GEMM: C[M,N] = A[M,Kd] * B[Kd,N], row-major.
// Block tile 128x128, BK=16. 256 threads = 8 warps (4 m x 2 n), each warp
// computes 32x64 via 2x8 m16n8k8 tf32 mma fragments.
// ---------------------------------------------------------------------------
#define AS_STRIDE 136   // 136 mod 32 == 8 -> conflict-free fragment loads

__global__ __launch_bounds__(256) void sgemm_tf32(
    const float* __restrict__ A, const float* __restrict__ B,
    float* __restrict__ C, int M, int N, int Kd) {
  __shared__ uint32_t As[16 * AS_STRIDE];   // As[k][m] (transposed)
  __shared__ uint32_t Bs[16 * AS_STRIDE];   // Bs[k][n]

  const int tid = threadIdx.x;
  const int warp = tid >> 5, lane = tid & 31;
  const int g = lane >> 2, tc = lane & 3;
  const int wm = warp & 3, wn = warp >> 2;
  const int m_base = wm * 32;
  const int n_base = wn * 64;
  const int crow = blockIdx.y * 128;
  const int ccol = blockIdx.x * 128;

  const int aRow = tid >> 1;          // 0..127
  const int aColH = (tid & 1) * 8;    // 0 or 8
  const int bRow = tid >> 4;          // 0..15
  const int bCol = (tid & 15) * 8;    // 0..120

  const float* Ap = A + (size_t)(crow + aRow) * Kd + aColH;
  const float* Bp = B + (size_t)bRow * N + ccol + bCol;

  float acc[2][8][4];
  #pragma unroll
  for (int mi = 0; mi < 2; mi++)
    #pragma unroll
    for (int ni = 0; ni < 8; ni++)
      #pragma unroll
      for (int r = 0; r < 4; r++) acc[mi][ni][r] = 0.0f;

  for (int k0 = 0; k0 < Kd; k0 += 16) {
    {
      float4 x = *(const float4*)Ap;
      float4 y = *(const float4*)(Ap + 4);
      As[(aColH + 0) * AS_STRIDE + aRow] = f2tf32(x.x);
      As[(aColH + 1) * AS_STRIDE + aRow] = f2tf32(x.y);
      As[(aColH + 2) * AS_STRIDE + aRow] = f2tf32(x.z);
      As[(aColH + 3) * AS_STRIDE + aRow] = f2tf32(x.w);
      As[(aColH + 4) * AS_STRIDE + aRow] = f2tf32(y.x);
      As[(aColH + 5) * AS_STRIDE + aRow] = f2tf32(y.y);
      As[(aColH + 6) * AS_STRIDE + aRow] = f2tf32(y.z);
      As[(aColH + 7) * AS_STRIDE + aRow] = f2tf32(y.w);
    }
    {
      float4 x = *(const float4*)Bp;
      float4 y = *(const float4*)(Bp + 4);
      uint32_t* dst = &Bs[bRow * AS_STRIDE + bCol];
      dst[0] = f2tf32(x.x); dst[1] = f2tf32(x.y);
      dst[2] = f2tf32(x.z); dst[3] = f2tf32(x.w);
      dst[4] = f2tf32(y.x); dst[5] = f2tf32(y.y);
      dst[6] = f2tf32(y.z); dst[7] = f2tf32(y.w);
    }
    __syncthreads();
    Ap += 16;
    Bp += (size_t)16 * N;

    #pragma unroll
    for (int ks = 0; ks < 16; ks += 8) {
      uint32_t afr[2][4];
      #pragma unroll
      for (int mi = 0; mi < 2; mi++) {
        int base = (ks + tc) * AS_STRIDE + m_base + mi * 16 + g;
        afr[mi][0] = As[base];
        afr[mi][1] = As[base + 8];
        afr[mi][2] = As[base + 4 * AS_STRIDE];
        afr[mi][3] = As[base + 4 * AS_STRIDE + 8];
      }
      uint32_t bfr[8][2];
      #pragma unroll
      for (int ni = 0; ni < 8; ni++) {
        int base = (ks + tc) * AS_STRIDE + n_base + ni * 8 + g;
        bfr[ni][0] = Bs[base];
        bfr[ni][1] = Bs[base + 4 * AS_STRIDE];
      }
      #pragma unroll
      for (int mi = 0; mi < 2; mi++)
        #pragma unroll
        for (int ni = 0; ni < 8; ni++)
          mma_tf32(acc[mi][ni], afr[mi], bfr[ni][0], bfr[ni][1]);
    }
    __syncthreads();
  }

  #pragma unroll
  for (int mi = 0; mi < 2; mi++) {
    #pragma unroll
    for (int ni = 0; ni < 8; ni++) {
      int row = crow + m_base + mi * 16 + g;
      int col = ccol + n_base + ni * 8 + 2 * tc;
      *(float2*)&C[(size_t)row * N + col] =
          make_float2(acc[mi][ni][0], acc[mi][ni][1]);
      *(float2*)&C[(size_t)(row + 8) * N + col] =
          make_float2(acc[mi][ni][2], acc[mi][ni][3]);
    }
  }
}

// ---------------------------------------------------------------------------
// RoPE applied in-place to q and k (first ROT dims of each head)
// ---------------------------------------------------------------------------
__global__ void rope_kernel(float* __restrict__ q, float* __restrict__ k,
                            const float* __restrict__ rot) {
  int idx = blockIdx.x * 256 + threadIdx.x;
  const int total = MROWS * HH * (ROT / 2);
  if (idx >= total) return;
  int i = idx & 15;
  int h = (idx >> 4) & 15;
  int row = idx >> 8;
  int l = row & (LL - 1);

  float f0 = rot[l * ROT + 2 * i];
  float f1 = rot[l * ROT + 2 * i + 1];
  float s0, c0, s1, c1;
  sincosf(f0, &s0, &c0);
  sincosf(f1, &s1, &c1);

  int base = row * DD + h * KK + 2 * i;
  float2 tq = *(float2*)&q[base];
  float2 tk = *(float2*)&k[base];
  float2 oq, ok;
  oq.x = tq.x * c0 - tq.y * s0;
  oq.y = tq.y * c1 + tq.x * s1;
  ok.x = tk.x * c0 - tk.y * s0;
  ok.y = tk.y * c1 + tk.x * s1;
  *(float2*)&q[base] = oq;
  *(float2*)&k[base] = ok;
}

// ---------------------------------------------------------------------------
// Flash attention with TF32 tensor cores.
// Block: (b, h, 128 q-rows). 256 threads = 8 warps; warp w owns rows
// w*16..w*16+15 (one m16 tile) across all 64 kv cols / 64 d cols.
// Softmax is warp-local. smem (uint32/tf32 bits):
//   Qs[128][68] (pre-scaled 1/sqrt(K)), Ks[tok][68], Vs[d][68] (V transposed),
//   Ps[128][68].
// ---------------------------------------------------------------------------
#define FS 68   // smem row stride; 68 mod 32 == 4 -> conflict-free fragments
#define FA_SMEM_WORDS (128 * FS + 64 * FS + 64 * FS + 128 * FS)
#define FA_SMEM_BYTES (FA_SMEM_WORDS * 4)

__global__ __launch_bounds__(256) void flash_attn_tc(
    const float* __restrict__ gq, const float* __restrict__ gk,
    const float* __restrict__ gv, float* __restrict__ gctx) {
  extern __shared__ uint32_t usm[];
  uint32_t* Qs = usm;               // [128][FS]
  uint32_t* Ks = Qs + 128 * FS;     // [64][FS]   Ks[tok][d]
  uint32_t* Vs = Ks + 64 * FS;      // [64][FS]   Vs[d][tok]
  uint32_t* Ps = Vs + 64 * FS;      // [128][FS]  Ps[row][kv]

  const int tid = threadIdx.x;
  const int warp = tid >> 5, lane = tid & 31;
  const int g = lane >> 2, tc = lane & 3;
  const int qt = blockIdx.x, h = blockIdx.y, b = blockIdx.z;
  const int qrow0 = b * LL + qt * 128;
  const int hoff = h * KK;
  const int wrow = warp * 16;   // warp's first q row in tile

  // Load Q tile, pre-scaled by 1/sqrt(64)=0.125
  {
    int r = tid >> 1;
    int d0 = (tid & 1) * 32;
    const float* src = gq + (size_t)(qrow0 + r) * DD + hoff + d0;
    uint32_t* dst = &Qs[r * FS + d0];
    #pragma unroll
    for (int u = 0; u < 8; u++) {
      float4 x = *(const float4*)(src + 4 * u);
      dst[4 * u + 0] = f2tf32(0.125f * x.x);
      dst[4 * u + 1] = f2tf32(0.125f * x.y);
      dst[4 * u + 2] = f2tf32(0.125f * x.z);
      dst[4 * u + 3] = f2tf32(0.125f * x.w);
    }
  }

  float o[8][4];
  #pragma unroll
  for (int ni = 0; ni < 8; ni++)
    #pragma unroll
    for (int r = 0; r < 4; r++) o[ni][r] = 0.0f;
  float mrow0 = -1e30f, mrow1 = -1e30f;
  float lrow0 = 0.0f, lrow1 = 0.0f;

  for (int t = 0; t < LL / 64; t++) {
    // Load K [tok][d] and V transposed [d][tok]
    {
      int kbase = b * LL + t * 64;
      int tok = tid >> 2;
      int d0 = (tid & 3) * 16;
      const float* ks = gk + (size_t)(kbase + tok) * DD + hoff + d0;
      const float* vs = gv + (size_t)(kbase + tok) * DD + hoff + d0;
      #pragma unroll
      for (int u = 0; u < 4; u++) {
        float4 x = *(const float4*)(ks + 4 * u);
        uint32_t* kd = &Ks[tok * FS + d0 + 4 * u];
        kd[0] = f2tf32(x.x); kd[1] = f2tf32(x.y);
        kd[2] = f2tf32(x.z); kd[3] = f2tf32(x.w);
        float4 y = *(const float4*)(vs + 4 * u);
        Vs[(d0 + 4 * u + 0) * FS + tok] = f2tf32(y.x);
        Vs[(d0 + 4 * u + 1) * FS + tok] = f2tf32(y.y);
        Vs[(d0 + 4 * u + 2) * FS + tok] = f2tf32(y.z);
        Vs[(d0 + 4 * u + 3) * FS + tok] = f2tf32(y.w);
      }
    }
    __syncthreads();   // Ks, Vs (and first-iter Qs) visible

    // S = Q K^T : warp computes rows [wrow, wrow+16) x 64 kv
    float sacc[8][4];
    #pragma unroll
    for (int ni = 0; ni < 8; ni++)
      #pragma unroll
      for (int r = 0; r < 4; r++) sacc[ni][r] = 0.0f;

    #pragma unroll
    for (int ks = 0; ks < 8; ks++) {
      uint32_t a[4];
      int ab = (wrow + g) * FS + ks * 8 + tc;
      a[0] = Qs[ab];
      a[1] = Qs[ab + 8 * FS];
      a[2] = Qs[ab + 4];
      a[3] = Qs[ab + 8 * FS + 4];
      #pragma unroll
      for (int ni = 0; ni < 8; ni++) {
        int bb2 = (ni * 8 + g) * FS + ks * 8 + tc;
        mma_tf32(sacc[ni], a, Ks[bb2], Ks[bb2 + 4]);
      }
    }

    // Warp-local online softmax (rows g and g+8 of warp tile)
    float mx0 = -1e30f, mx1 = -1e30f;
    #pragma unroll
    for (int ni = 0; ni < 8; ni++) {
      mx0 = fmaxf(mx0, fmaxf(sacc[ni][0], sacc[ni][1]));
      mx1 = fmaxf(mx1, fmaxf(sacc[ni][2], sacc[ni][3]));
    }
    mx0 = fmaxf(mx0, __shfl_xor_sync(0xffffffffu, mx0, 1));
    mx0 = fmaxf(mx0, __shfl_xor_sync(0xffffffffu, mx0, 2));
    mx1 = fmaxf(mx1, __shfl_xor_sync(0xffffffffu, mx1, 1));
    mx1 = fmaxf(mx1, __shfl_xor_sync(0xffffffffu, mx1, 2));

    float mn0 = fmaxf(mrow0, mx0);
    float mn1 = fmaxf(mrow1, mx1);
    float corr0 = __expf(mrow0 - mn0);
    float corr1 = __expf(mrow1 - mn1);
    mrow0 = mn0; mrow1 = mn1;

    float ls0 = 0.0f, ls1 = 0.0f;
    #pragma unroll
    for (int ni = 0; ni < 8; ni++) {
      float p00 = __expf(sacc[ni][0] - mn0);
      float p01 = __expf(sacc[ni][1] - mn0);
      float p10 = __expf(sacc[ni][2] - mn1);
      float p11 = __expf(sacc[ni][3] - mn1);
      ls0 += p00 + p01;
      ls1 += p10 + p11;
      int col = ni * 8 + 2 * tc;
      uint32_t* p0 = &Ps[(wrow + g) * FS + col];
      p0[0] = f2tf32(p00); p0[1] = f2tf32(p01);
      uint32_t* p1 = &Ps[(wrow + g + 8) * FS + col];
      p1[0] = f2tf32(p10); p1[1] = f2tf32(p11);
    }
    ls0 += __shfl_xor_sync(0xffffffffu, ls0, 1);
    ls0 += __shfl_xor_sync(0xffffffffu, ls0, 2);
    ls1 += __shfl_xor_sync(0xffffffffu, ls1, 1);
    ls1 += __shfl_xor_sync(0xffffffffu, ls1, 2);
    lrow0 = lrow0 * corr0 + ls0;
    lrow1 = lrow1 * corr1 + ls1;

    #pragma unroll
    for (int ni = 0; ni < 8; ni++) {
      o[ni][0] *= corr0; o[ni][1] *= corr0;
      o[ni][2] *= corr1; o[ni][3] *= corr1;
    }
    __syncwarp();   // warp's own P rows written by warp's own threads

    // O += P @ V : A from Ps (warp's rows), B from Vs (V^T)
    #pragma unroll
    for (int ks = 0; ks < 8; ks++) {
      uint32_t a[4];
      int ab = (wrow + g) * FS + ks * 8 + tc;
      a[0] = Ps[ab];
      a[1] = Ps[ab + 8 * FS];
      a[2] = Ps[ab + 4];
      a[3] = Ps[ab + 8 * FS + 4];
      #pragma unroll
      for (int ni = 0; ni < 8; ni++) {
        int bb2 = (ni * 8 + g) * FS + ks * 8 + tc;
        mma_tf32(o[ni], a, Vs[bb2], Vs[bb2 + 4]);
      }
    }
    __syncthreads();   // Ks/Vs reads done before next tile's loads
  }

  // Normalize and store
  float inv0 = 1.0f / lrow0;
  float inv1 = 1.0f / lrow1;
  #pragma unroll
  for (int ni = 0; ni < 8; ni++) {
    int col = hoff + ni * 8 + 2 * tc;
    int row0 = qrow0 + wrow + g;
    *(float2*)&gctx[(size_t)row0 * DD + col] =
        make_float2(o[ni][0] * inv0, o[ni][1] * inv0);
    *(float2*)&gctx[(size_t)(row0 + 8) * DD + col] =
        make_float2(o[ni][2] * inv1, o[ni][3] * inv1);
  }
}

// ---------------------------------------------------------------------------
extern "C" void kernel_launch(void* const* d_in, const int* in_sizes, int n_in,
                              void* d_out, int out_size) {
  const float* query    = (const float*)d_in[0];
  const float* key      = (const float*)d_in[1];
  const float* value    = (const float*)d_in[2];
  const float* rot      = (const float*)d_in[3];
  const float* q_kernel = (const float*)d_in[4];
  const float* k_kernel = (const float*)d_in[5];
  const float* v_kernel = (const float*)d_in[6];
  const float* o_kernel = (const float*)d_in[7];
  float* out = (float*)d_out;

  float *pq, *pk, *pv, *pctx;
  cudaGetSymbolAddress((void**)&pq, g_q);
  cudaGetSymbolAddress((void**)&pk, g_k);
  cudaGetSymbolAddress((void**)&pv, g_v);
  cudaGetSymbolAddress((void**)&pctx, g_ctx);

  dim3 gemm_grid(DD / 128, MROWS / 128);   // (8, 32)

  // QKV projections (tf32 tensor cores)
  sgemm_tf32<<<gemm_grid, 256>>>(query, q_kernel, pq, MROWS, DD, DD);
  sgemm_tf32<<<gemm_grid, 256>>>(key,   k_kernel, pk, MROWS, DD, DD);
  sgemm_tf32<<<gemm_grid, 256>>>(value, v_kernel, pv, MROWS, DD, DD);

  // RoPE on q, k
  {
    int total = MROWS * HH * (ROT / 2);
    rope_kernel<<<(total + 255) / 256, 256>>>(pq, pk, rot);
  }

  // Flash attention (tf32 tensor cores)
  cudaFuncSetAttribute(flash_attn_tc, cudaFuncAttributeMaxDynamicSharedMemorySize,
                       FA_SMEM_BYTES);
  flash_attn_tc<<<dim3(LL / 128, HH, BB), 256, FA_SMEM_BYTES>>>(pq, pk, pv, pctx);

  // Output projection (tf32 tensor cores)
  sgemm_tf32<<<gemm_grid, 256>>>(pctx, o_kernel, out, MROWS, DD, DD);
}

// round 6
// speedup vs baseline: 2.4105x; 1.0446x over previous
#include <cuda_runtime.h>
#include <math.h>
#include <stdint.h>

// Problem constants
#define BB 2
#define LL 2048
#define DD 1024
#define HH 16
#define KK 64
#define ROT 32
#define MROWS (BB * LL)   // 4096

// Scratch (static device arrays: allocation-free)
__device__ float g_q[MROWS * DD];
__device__ float g_k[MROWS * DD];
__device__ float g_v[MROWS * DD];
__device__ float g_ctx[MROWS * DD];

__device__ __forceinline__ uint32_t f2tf32(float f) {
  uint32_t u;
  asm("cvt.rna.tf32.f32 %0, %1;" : "=r"(u) : "f"(f));
  return u;
}

__device__ __forceinline__ void mma_tf32(float c[4], const uint32_t a[4],
                                         uint32_t b0, uint32_t b1) {
  asm("mma.sync.aligned.m16n8k8.row.col.f32.tf32.tf32.f32 "
      "{%0,%1,%2,%3},{%4,%5,%6,%7},{%8,%9},{%0,%1,%2,%3};"
      : "+f"(c[0]), "+f"(c[1]), "+f"(c[2]), "+f"(c[3])
      : "r"(a[0]), "r"(a[1]), "r"(a[2]), "r"(a[3]), "r"(b0), "r"(b1));
}

// ---------------------------------------------------------------------------
// TF32 tensor-core GEMM, double-buffered smem + register prefetch.
// C[M,N] = A[M,Kd] * B[Kd,N], row-major. Block tile 128x128, BK=16.
// 256 threads = 8 warps (4m x 2n), warp computes 32x64 (2x8 m16n8k8 frags).
// grid.z selects (A,C) pair -> QKV projections fused into one launch.
// ---------------------------------------------------------------------------
#define AS_STRIDE 136   // 136 mod 32 == 8 -> conflict-free fragment loads

__global__ __launch_bounds__(256, 2) void sgemm_tf32_db(
    const float* __restrict__ A0, const float* __restrict__ A1,
    const float* __restrict__ A2, const float* __restrict__ B0,
    const float* __restrict__ B1, const float* __restrict__ B2,
    float* __restrict__ C0, float* __restrict__ C1, float* __restrict__ C2,
    int M, int N, int Kd) {
  __shared__ uint32_t As[2][16 * AS_STRIDE];   // As[buf][k][m] (transposed)
  __shared__ uint32_t Bs[2][16 * AS_STRIDE];   // Bs[buf][k][n]

  const int z = blockIdx.z;
  const float* A = (z == 0) ? A0 : (z == 1) ? A1 : A2;
  const float* B = (z == 0) ? B0 : (z == 1) ? B1 : B2;
  float* C = (z == 0) ? C0 : (z == 1) ? C1 : C2;

  const int tid = threadIdx.x;
  const int warp = tid >> 5, lane = tid & 31;
  const int g = lane >> 2, tc = lane & 3;
  const int wm = warp & 3, wn = warp >> 2;
  const int m_base = wm * 32;
  const int n_base = wn * 64;
  const int crow = blockIdx.y * 128;
  const int ccol = blockIdx.x * 128;

  const int aRow = tid >> 1;          // 0..127
  const int aColH = (tid & 1) * 8;    // 0 or 8
  const int bRow = tid >> 4;          // 0..15
  const int bCol = (tid & 15) * 8;    // 0..120

  const float* Ap = A + (size_t)(crow + aRow) * Kd + aColH;
  const float* Bp = B + (size_t)bRow * N + ccol + bCol;

  float acc[2][8][4];
  #pragma unroll
  for (int mi = 0; mi < 2; mi++)
    #pragma unroll
    for (int ni = 0; ni < 8; ni++)
      #pragma unroll
      for (int r = 0; r < 4; r++) acc[mi][ni][r] = 0.0f;

  // Prologue: load tile 0 into regs, store to buffer 0
  float4 ra0 = *(const float4*)Ap;
  float4 ra1 = *(const float4*)(Ap + 4);
  float4 rb0 = *(const float4*)Bp;
  float4 rb1 = *(const float4*)(Bp + 4);
  Ap += 16;
  Bp += (size_t)16 * N;
  {
    uint32_t* as = As[0];
    as[(aColH + 0) * AS_STRIDE + aRow] = f2tf32(ra0.x);
    as[(aColH + 1) * AS_STRIDE + aRow] = f2tf32(ra0.y);
    as[(aColH + 2) * AS_STRIDE + aRow] = f2tf32(ra0.z);
    as[(aColH + 3) * AS_STRIDE + aRow] = f2tf32(ra0.w);
    as[(aColH + 4) * AS_STRIDE + aRow] = f2tf32(ra1.x);
    as[(aColH + 5) * AS_STRIDE + aRow] = f2tf32(ra1.y);
    as[(aColH + 6) * AS_STRIDE + aRow] = f2tf32(ra1.z);
    as[(aColH + 7) * AS_STRIDE + aRow] = f2tf32(ra1.w);
    uint32_t* bs = &Bs[0][bRow * AS_STRIDE + bCol];
    bs[0] = f2tf32(rb0.x); bs[1] = f2tf32(rb0.y);
    bs[2] = f2tf32(rb0.z); bs[3] = f2tf32(rb0.w);
    bs[4] = f2tf32(rb1.x); bs[5] = f2tf32(rb1.y);
    bs[6] = f2tf32(rb1.z); bs[7] = f2tf32(rb1.w);
  }
  __syncthreads();

  int buf = 0;
  const int iters = Kd / 16;
  for (int it = 0; it < iters; it++) {
    const bool last = (it == iters - 1);
    // Prefetch next tile into registers (latency hidden by compute below)
    if (!last) {
      ra0 = *(const float4*)Ap;
      ra1 = *(const float4*)(Ap + 4);
      rb0 = *(const float4*)Bp;
      rb1 = *(const float4*)(Bp + 4);
      Ap += 16;
      Bp += (size_t)16 * N;
    }

    // Compute on current buffer
    const uint32_t* asb = As[buf];
    const uint32_t* bsb = Bs[buf];
    #pragma unroll
    for (int ks = 0; ks < 16; ks += 8) {
      uint32_t afr[2][4];
      #pragma unroll
      for (int mi = 0; mi < 2; mi++) {
        int base = (ks + tc) * AS_STRIDE + m_base + mi * 16 + g;
        afr[mi][0] = asb[base];
        afr[mi][1] = asb[base + 8];
        afr[mi][2] = asb[base + 4 * AS_STRIDE];
        afr[mi][3] = asb[base + 4 * AS_STRIDE + 8];
      }
      uint32_t bfr[8][2];
      #pragma unroll
      for (int ni = 0; ni < 8; ni++) {
        int base = (ks + tc) * AS_STRIDE + n_base + ni * 8 + g;
        bfr[ni][0] = bsb[base];
        bfr[ni][1] = bsb[base + 4 * AS_STRIDE];
      }
      #pragma unroll
      for (int mi = 0; mi < 2; mi++)
        #pragma unroll
        for (int ni = 0; ni < 8; ni++)
          mma_tf32(acc[mi][ni], afr[mi], bfr[ni][0], bfr[ni][1]);
    }

    // Store prefetched tile into the other buffer
    if (!last) {
      uint32_t* as = As[buf ^ 1];
      as[(aColH + 0) * AS_STRIDE + aRow] = f2tf32(ra0.x);
      as[(aColH + 1) * AS_STRIDE + aRow] = f2tf32(ra0.y);
      as[(aColH + 2) * AS_STRIDE + aRow] = f2tf32(ra0.z);
      as[(aColH + 3) * AS_STRIDE + aRow] = f2tf32(ra0.w);
      as[(aColH + 4) * AS_STRIDE + aRow] = f2tf32(ra1.x);
      as[(aColH + 5) * AS_STRIDE + aRow] = f2tf32(ra1.y);
      as[(aColH + 6) * AS_STRIDE + aRow] = f2tf32(ra1.z);
      as[(aColH + 7) * AS_STRIDE + aRow] = f2tf32(ra1.w);
      uint32_t* bs = &Bs[buf ^ 1][bRow * AS_STRIDE + bCol];
      bs[0] = f2tf32(rb0.x); bs[1] = f2tf32(rb0.y);
      bs[2] = f2tf32(rb0.z); bs[3] = f2tf32(rb0.w);
      bs[4] = f2tf32(rb1.x); bs[5] = f2tf32(rb1.y);
      bs[6] = f2tf32(rb1.z); bs[7] = f2tf32(rb1.w);
      __syncthreads();
      buf ^= 1;
    }
  }

  #pragma unroll
  for (int mi = 0; mi < 2; mi++) {
    #pragma unroll
    for (int ni = 0; ni < 8; ni++) {
      int row = crow + m_base + mi * 16 + g;
      int col = ccol + n_base + ni * 8 + 2 * tc;
      *(float2*)&C[(size_t)row * N + col] =
          make_float2(acc[mi][ni][0], acc[mi][ni][1]);
      *(float2*)&C[(size_t)(row + 8) * N + col] =
          make_float2(acc[mi][ni][2], acc[mi][ni][3]);
    }
  }
}

// ---------------------------------------------------------------------------
// RoPE applied in-place to q and k (first ROT dims of each head)
// ---------------------------------------------------------------------------
__global__ void rope_kernel(float* __restrict__ q, float* __restrict__ k,
                            const float* __restrict__ rot) {
  int idx = blockIdx.x * 256 + threadIdx.x;
  const int total = MROWS * HH * (ROT / 2);
  if (idx >= total) return;
  int i = idx & 15;
  int h = (idx >> 4) & 15;
  int row = idx >> 8;
  int l = row & (LL - 1);

  float f0 = rot[l * ROT + 2 * i];
  float f1 = rot[l * ROT + 2 * i + 1];
  float s0, c0, s1, c1;
  sincosf(f0, &s0, &c0);
  sincosf(f1, &s1, &c1);

  int base = row * DD + h * KK + 2 * i;
  float2 tq = *(float2*)&q[base];
  float2 tk = *(float2*)&k[base];
  float2 oq, ok;
  oq.x = tq.x * c0 - tq.y * s0;
  oq.y = tq.y * c1 + tq.x * s1;
  ok.x = tk.x * c0 - tk.y * s0;
  ok.y = tk.y * c1 + tk.x * s1;
  *(float2*)&q[base] = oq;
  *(float2*)&k[base] = ok;
}

// ---------------------------------------------------------------------------
// Flash attention with TF32 tensor cores (unchanged from R5 passing version).
// ---------------------------------------------------------------------------
#define FS 68   // smem row stride; 68 mod 32 == 4 -> conflict-free fragments
#define FA_SMEM_WORDS (128 * FS + 64 * FS + 64 * FS + 128 * FS)
#define FA_SMEM_BYTES (FA_SMEM_WORDS * 4)

__global__ __launch_bounds__(256) void flash_attn_tc(
    const float* __restrict__ gq, const float* __restrict__ gk,
    const float* __restrict__ gv, float* __restrict__ gctx) {
  extern __shared__ uint32_t usm[];
  uint32_t* Qs = usm;               // [128][FS]
  uint32_t* Ks = Qs + 128 * FS;     // [64][FS]   Ks[tok][d]
  uint32_t* Vs = Ks + 64 * FS;      // [64][FS]   Vs[d][tok]
  uint32_t* Ps = Vs + 64 * FS;      // [128][FS]  Ps[row][kv]

  const int tid = threadIdx.x;
  const int warp = tid >> 5, lane = tid & 31;
  const int g = lane >> 2, tc = lane & 3;
  const int qt = blockIdx.x, h = blockIdx.y, b = blockIdx.z;
  const int qrow0 = b * LL + qt * 128;
  const int hoff = h * KK;
  const int wrow = warp * 16;   // warp's first q row in tile

  // Load Q tile, pre-scaled by 1/sqrt(64)=0.125
  {
    int r = tid >> 1;
    int d0 = (tid & 1) * 32;
    const float* src = gq + (size_t)(qrow0 + r) * DD + hoff + d0;
    uint32_t* dst = &Qs[r * FS + d0];
    #pragma unroll
    for (int u = 0; u < 8; u++) {
      float4 x = *(const float4*)(src + 4 * u);
      dst[4 * u + 0] = f2tf32(0.125f * x.x);
      dst[4 * u + 1] = f2tf32(0.125f * x.y);
      dst[4 * u + 2] = f2tf32(0.125f * x.z);
      dst[4 * u + 3] = f2tf32(0.125f * x.w);
    }
  }

  float o[8][4];
  #pragma unroll
  for (int ni = 0; ni < 8; ni++)
    #pragma unroll
    for (int r = 0; r < 4; r++) o[ni][r] = 0.0f;
  float mrow0 = -1e30f, mrow1 = -1e30f;
  float lrow0 = 0.0f, lrow1 = 0.0f;

  for (int t = 0; t < LL / 64; t++) {
    // Load K [tok][d] and V transposed [d][tok]
    {
      int kbase = b * LL + t * 64;
      int tok = tid >> 2;
      int d0 = (tid & 3) * 16;
      const float* ks = gk + (size_t)(kbase + tok) * DD + hoff + d0;
      const float* vs = gv + (size_t)(kbase + tok) * DD + hoff + d0;
      #pragma unroll
      for (int u = 0; u < 4; u++) {
        float4 x = *(const float4*)(ks + 4 * u);
        uint32_t* kd = &Ks[tok * FS + d0 + 4 * u];
        kd[0] = f2tf32(x.x); kd[1] = f2tf32(x.y);
        kd[2] = f2tf32(x.z); kd[3] = f2tf32(x.w);
        float4 y = *(const float4*)(vs + 4 * u);
        Vs[(d0 + 4 * u + 0) * FS + tok] = f2tf32(y.x);
        Vs[(d0 + 4 * u + 1) * FS + tok] = f2tf32(y.y);
        Vs[(d0 + 4 * u + 2) * FS + tok] = f2tf32(y.z);
        Vs[(d0 + 4 * u + 3) * FS + tok] = f2tf32(y.w);
      }
    }
    __syncthreads();   // Ks, Vs (and first-iter Qs) visible

    // S = Q K^T : warp computes rows [wrow, wrow+16) x 64 kv
    float sacc[8][4];
    #pragma unroll
    for (int ni = 0; ni < 8; ni++)
      #pragma unroll
      for (int r = 0; r < 4; r++) sacc[ni][r] = 0.0f;

    #pragma unroll
    for (int ks = 0; ks < 8; ks++) {
      uint32_t a[4];
      int ab = (wrow + g) * FS + ks * 8 + tc;
      a[0] = Qs[ab];
      a[1] = Qs[ab + 8 * FS];
      a[2] = Qs[ab + 4];
      a[3] = Qs[ab + 8 * FS + 4];
      #pragma unroll
      for (int ni = 0; ni < 8; ni++) {
        int bb2 = (ni * 8 + g) * FS + ks * 8 + tc;
        mma_tf32(sacc[ni], a, Ks[bb2], Ks[bb2 + 4]);
      }
    }

    // Warp-local online softmax (rows g and g+8 of warp tile)
    float mx0 = -1e30f, mx1 = -1e30f;
    #pragma unroll
    for (int ni = 0; ni < 8; ni++) {
      mx0 = fmaxf(mx0, fmaxf(sacc[ni][0], sacc[ni][1]));
      mx1 = fmaxf(mx1, fmaxf(sacc[ni][2], sacc[ni][3]));
    }
    mx0 = fmaxf(mx0, __shfl_xor_sync(0xffffffffu, mx0, 1));
    mx0 = fmaxf(mx0, __shfl_xor_sync(0xffffffffu, mx0, 2));
    mx1 = fmaxf(mx1, __shfl_xor_sync(0xffffffffu, mx1, 1));
    mx1 = fmaxf(mx1, __shfl_xor_sync(0xffffffffu, mx1, 2));

    float mn0 = fmaxf(mrow0, mx0);
    float mn1 = fmaxf(mrow1, mx1);
    float corr0 = __expf(mrow0 - mn0);
    float corr1 = __expf(mrow1 - mn1);
    mrow0 = mn0; mrow1 = mn1;

    float ls0 = 0.0f, ls1 = 0.0f;
    #pragma unroll
    for (int ni = 0; ni < 8; ni++) {
      float p00 = __expf(sacc[ni][0] - mn0);
      float p01 = __expf(sacc[ni][1] - mn0);
      float p10 = __expf(sacc[ni][2] - mn1);
      float p11 = __expf(sacc[ni][3] - mn1);
      ls0 += p00 + p01;
      ls1 += p10 + p11;
      int col = ni * 8 + 2 * tc;
      uint32_t* p0 = &Ps[(wrow + g) * FS + col];
      p0[0] = f2tf32(p00); p0[1] = f2tf32(p01);
      uint32_t* p1 = &Ps[(wrow + g + 8) * FS + col];
      p1[0] = f2tf32(p10); p1[1] = f2tf32(p11);
    }
    ls0 += __shfl_xor_sync(0xffffffffu, ls0, 1);
    ls0 += __shfl_xor_sync(0xffffffffu, ls0, 2);
    ls1 += __shfl_xor_sync(0xffffffffu, ls1, 1);
    ls1 += __shfl_xor_sync(0xffffffffu, ls1, 2);
    lrow0 = lrow0 * corr0 + ls0;
    lrow1 = lrow1 * corr1 + ls1;

    #pragma unroll
    for (int ni = 0; ni < 8; ni++) {
      o[ni][0] *= corr0; o[ni][1] *= corr0;
      o[ni][2] *= corr1; o[ni][3] *= corr1;
    }
    __syncwarp();   // warp's own P rows written by warp's own threads

    // O += P @ V : A from Ps (warp's rows), B from Vs (V^T)
    #pragma unroll
    for (int ks = 0; ks < 8; ks++) {
      uint32_t a[4];
      int ab = (wrow + g) * FS + ks * 8 + tc;
      a[0] = Ps[ab];
      a[1] = Ps[ab + 8 * FS];
      a[2] = Ps[ab + 4];
      a[3] = Ps[ab + 8 * FS + 4];
      #pragma unroll
      for (int ni = 0; ni < 8; ni++) {
        int bb2 = (ni * 8 + g) * FS + ks * 8 + tc;
        mma_tf32(o[ni], a, Vs[bb2], Vs[bb2 + 4]);
      }
    }
    __syncthreads();   // Ks/Vs reads done before next tile's loads
  }

  // Normalize and store
  float inv0 = 1.0f / lrow0;
  float inv1 = 1.0f / lrow1;
  #pragma unroll
  for (int ni = 0; ni < 8; ni++) {
    int col = hoff + ni * 8 + 2 * tc;
    int row0 = qrow0 + wrow + g;
    *(float2*)&gctx[(size_t)row0 * DD + col] =
        make_float2(o[ni][0] * inv0, o[ni][1] * inv0);
    *(float2*)&gctx[(size_t)(row0 + 8) * DD + col] =
        make_float2(o[ni][2] * inv1, o[ni][3] * inv1);
  }
}

// ---------------------------------------------------------------------------
extern "C" void kernel_launch(void* const* d_in, const int* in_sizes, int n_in,
                              void* d_out, int out_size) {
  const float* query    = (const float*)d_in[0];
  const float* key      = (const float*)d_in[1];
  const float* value    = (const float*)d_in[2];
  const float* rot      = (const float*)d_in[3];
  const float* q_kernel = (const float*)d_in[4];
  const float* k_kernel = (const float*)d_in[5];
  const float* v_kernel = (const float*)d_in[6];
  const float* o_kernel = (const float*)d_in[7];
  float* out = (float*)d_out;

  float *pq, *pk, *pv, *pctx;
  cudaGetSymbolAddress((void**)&pq, g_q);
  cudaGetSymbolAddress((void**)&pk, g_k);
  cudaGetSymbolAddress((void**)&pv, g_v);
  cudaGetSymbolAddress((void**)&pctx, g_ctx);

  // QKV projections fused into one launch (grid.z selects A/B/C)
  sgemm_tf32_db<<<dim3(DD / 128, MROWS / 128, 3), 256>>>(
      query, key, value, q_kernel, k_kernel, v_kernel, pq, pk, pv,
      MROWS, DD, DD);

  // RoPE on q, k
  {
    int total = MROWS * HH * (ROT / 2);
    rope_kernel<<<(total + 255) / 256, 256>>>(pq, pk, rot);
  }

  // Flash attention (tf32 tensor cores)
  cudaFuncSetAttribute(flash_attn_tc, cudaFuncAttributeMaxDynamicSharedMemorySize,
                       FA_SMEM_BYTES);
  flash_attn_tc<<<dim3(LL / 128, HH, BB), 256, FA_SMEM_BYTES>>>(pq, pk, pv, pctx);

  // Output projection
  sgemm_tf32_db<<<dim3(DD / 128, MROWS / 128, 1), 256>>>(
      pctx, pctx, pctx, o_kernel, o_kernel, o_kernel, out, out, out,
      MROWS, DD, DD);
}

// round 9
// speedup vs baseline: 2.6891x; 1.1156x over previous
#include <cuda_runtime.h>
#include <math.h>
#include <stdint.h>

// Problem constants
#define BB 2
#define LL 2048
#define DD 1024
#define HH 16
#define KK 64
#define ROT 32
#define MROWS (BB * LL)   // 4096

// Scratch (static device arrays: allocation-free)
__device__ float g_q[MROWS * DD];
__device__ float g_k[MROWS * DD];
__device__ float g_v[MROWS * DD];
__device__ float g_ctx[MROWS * DD];

__device__ __forceinline__ uint32_t f2tf32(float f) {
  uint32_t u;
  asm("cvt.rna.tf32.f32 %0, %1;" : "=r"(u) : "f"(f));
  return u;
}

__device__ __forceinline__ void mma_tf32(float c[4], const uint32_t a[4],
                                         uint32_t b0, uint32_t b1) {
  asm("mma.sync.aligned.m16n8k8.row.col.f32.tf32.tf32.f32 "
      "{%0,%1,%2,%3},{%4,%5,%6,%7},{%8,%9},{%0,%1,%2,%3};"
      : "+f"(c[0]), "+f"(c[1]), "+f"(c[2]), "+f"(c[3])
      : "r"(a[0]), "r"(a[1]), "r"(a[2]), "r"(a[3]), "r"(b0), "r"(b1));
}

__device__ __forceinline__ void ldsm_x4(uint32_t* r, uint32_t addr) {
  asm volatile("ldmatrix.sync.aligned.m8n8.x4.shared.b16 {%0,%1,%2,%3}, [%4];"
               : "=r"(r[0]), "=r"(r[1]), "=r"(r[2]), "=r"(r[3]) : "r"(addr));
}

__device__ __forceinline__ uint32_t s2u(const void* p) {
  return (uint32_t)__cvta_generic_to_shared(p);
}

// ---------------------------------------------------------------------------
// TF32 tensor-core GEMM, double-buffered, ldmatrix A fragments.
// C[M,N] = A[M,Kd] * B[Kd,N], row-major. Block 128x128, BK=16, 256 threads,
// 8 warps (4m x 2n), warp tile 32x64.
// A smem: [m][16 k words], 64B rows, chunk swizzle c^=(m>>1)&3 -> conflict-free
// STS.128 producer + ldmatrix.x4 consumer.
// B smem: [k][n] stride 136, scalar LDS (conflict-free).
// ---------------------------------------------------------------------------
#define AS_STRIDE 136
#define AK 16

__global__ __launch_bounds__(256, 2) void sgemm_tf32_db(
    const float* __restrict__ A0, const float* __restrict__ A1,
    const float* __restrict__ A2, const float* __restrict__ B0,
    const float* __restrict__ B1, const float* __restrict__ B2,
    float* __restrict__ C0, float* __restrict__ C1, float* __restrict__ C2,
    int M, int N, int Kd) {
  __shared__ uint32_t As[2][128 * AK];
  __shared__ uint32_t Bs[2][16 * AS_STRIDE];

  const int z = blockIdx.z;
  const float* A = (z == 0) ? A0 : (z == 1) ? A1 : A2;
  const float* B = (z == 0) ? B0 : (z == 1) ? B1 : B2;
  float* C = (z == 0) ? C0 : (z == 1) ? C1 : C2;

  const int tid = threadIdx.x;
  const int warp = tid >> 5, lane = tid & 31;
  const int g = lane >> 2, tc = lane & 3;
  const int wm = warp & 3, wn = warp >> 2;
  const int m_base = wm * 32;
  const int n_base = wn * 64;
  const int crow = blockIdx.y * 128;
  const int ccol = blockIdx.x * 128;

  // A producer: thread -> rows (pr, pr+64), chunk pc (coalesced LDG.128)
  const int pr = tid >> 2;         // 0..63
  const int pc = tid & 3;          // chunk 0..3
  const int psw = (pr >> 1) & 3;   // same for pr and pr+64
  const uint32_t pd0 = pr * AK + 4 * (pc ^ psw);
  const uint32_t pd1 = (pr + 64) * AK + 4 * (pc ^ psw);
  const float* Ap0 = A + (size_t)(crow + pr) * Kd + pc * 4;
  const float* Ap1 = Ap0 + (size_t)64 * Kd;

  // B producer (unchanged)
  const int bRow = tid >> 4;          // 0..15
  const int bCol = (tid & 15) * 8;    // 0..120
  const float* Bp = B + (size_t)bRow * N + ccol + bCol;

  // A consumer (ldmatrix): per-lane row + swizzle
  const int a_ln = m_base + (lane & 15);
  const int a_sw = (a_ln >> 1) & 3;
  const int a_hi = lane >> 4;   // chunk select within fragment

  float acc[2][8][4];
  #pragma unroll
  for (int mi = 0; mi < 2; mi++)
    #pragma unroll
    for (int ni = 0; ni < 8; ni++)
      #pragma unroll
      for (int r = 0; r < 4; r++) acc[mi][ni][r] = 0.0f;

  // Prologue: tile 0 -> buffer 0
  float4 xa0 = *(const float4*)Ap0;
  float4 xa1 = *(const float4*)Ap1;
  float4 xb0 = *(const float4*)Bp;
  float4 xb1 = *(const float4*)(Bp + 4);
  Ap0 += 16; Ap1 += 16;
  Bp += (size_t)16 * N;
  {
    uint32_t* as = As[0];
    *(uint4*)&as[pd0] = make_uint4(f2tf32(xa0.x), f2tf32(xa0.y), f2tf32(xa0.z), f2tf32(xa0.w));
    *(uint4*)&as[pd1] = make_uint4(f2tf32(xa1.x), f2tf32(xa1.y), f2tf32(xa1.z), f2tf32(xa1.w));
    uint32_t* bs = &Bs[0][bRow * AS_STRIDE + bCol];
    bs[0] = f2tf32(xb0.x); bs[1] = f2tf32(xb0.y);
    bs[2] = f2tf32(xb0.z); bs[3] = f2tf32(xb0.w);
    bs[4] = f2tf32(xb1.x); bs[5] = f2tf32(xb1.y);
    bs[6] = f2tf32(xb1.z); bs[7] = f2tf32(xb1.w);
  }
  __syncthreads();

  const uint32_t as_u[2] = {s2u(As[0]), s2u(As[1])};

  int buf = 0;
  const int iters = Kd / 16;
  for (int it = 0; it < iters; it++) {
    const bool last = (it == iters - 1);
    if (!last) {
      xa0 = *(const float4*)Ap0;
      xa1 = *(const float4*)Ap1;
      xb0 = *(const float4*)Bp;
      xb1 = *(const float4*)(Bp + 4);
      Ap0 += 16; Ap1 += 16;
      Bp += (size_t)16 * N;
    }

    const uint32_t au = as_u[buf];
    const uint32_t* bsb = Bs[buf];
    #pragma unroll
    for (int ksi = 0; ksi < 2; ksi++) {
      uint32_t afr[2][4];
      #pragma unroll
      for (int mi = 0; mi < 2; mi++) {
        uint32_t addr = au + (uint32_t)(a_ln + mi * 16) * 64 +
                        16u * (uint32_t)((2 * ksi + a_hi) ^ a_sw);
        ldsm_x4(afr[mi], addr);
      }
      uint32_t bfr[8][2];
      #pragma unroll
      for (int ni = 0; ni < 8; ni++) {
        int base = (ksi * 8 + tc) * AS_STRIDE + n_base + ni * 8 + g;
        bfr[ni][0] = bsb[base];
        bfr[ni][1] = bsb[base + 4 * AS_STRIDE];
      }
      #pragma unroll
      for (int mi = 0; mi < 2; mi++)
        #pragma unroll
        for (int ni = 0; ni < 8; ni++)
          mma_tf32(acc[mi][ni], afr[mi], bfr[ni][0], bfr[ni][1]);
    }

    if (!last) {
      uint32_t* as = As[buf ^ 1];
      *(uint4*)&as[pd0] = make_uint4(f2tf32(xa0.x), f2tf32(xa0.y), f2tf32(xa0.z), f2tf32(xa0.w));
      *(uint4*)&as[pd1] = make_uint4(f2tf32(xa1.x), f2tf32(xa1.y), f2tf32(xa1.z), f2tf32(xa1.w));
      uint32_t* bs = &Bs[buf ^ 1][bRow * AS_STRIDE + bCol];
      bs[0] = f2tf32(xb0.x); bs[1] = f2tf32(xb0.y);
      bs[2] = f2tf32(xb0.z); bs[3] = f2tf32(xb0.w);
      bs[4] = f2tf32(xb1.x); bs[5] = f2tf32(xb1.y);
      bs[6] = f2tf32(xb1.z); bs[7] = f2tf32(xb1.w);
      __syncthreads();
      buf ^= 1;
    }
  }

  #pragma unroll
  for (int mi = 0; mi < 2; mi++) {
    #pragma unroll
    for (int ni = 0; ni < 8; ni++) {
      int row = crow + m_base + mi * 16 + g;
      int col = ccol + n_base + ni * 8 + 2 * tc;
      *(float2*)&C[(size_t)row * N + col] =
          make_float2(acc[mi][ni][0], acc[mi][ni][1]);
      *(float2*)&C[(size_t)(row + 8) * N + col] =
          make_float2(acc[mi][ni][2], acc[mi][ni][3]);
    }
  }
}

// ---------------------------------------------------------------------------
// RoPE applied in-place to q and k (first ROT dims of each head)
// ---------------------------------------------------------------------------
__global__ void rope_kernel(float* __restrict__ q, float* __restrict__ k,
                            const float* __restrict__ rot) {
  int idx = blockIdx.x * 256 + threadIdx.x;
  const int total = MROWS * HH * (ROT / 2);
  if (idx >= total) return;
  int i = idx & 15;
  int h = (idx >> 4) & 15;
  int row = idx >> 8;
  int l = row & (LL - 1);

  float f0 = rot[l * ROT + 2 * i];
  float f1 = rot[l * ROT + 2 * i + 1];
  float s0, c0, s1, c1;
  sincosf(f0, &s0, &c0);
  sincosf(f1, &s1, &c1);

  int base = row * DD + h * KK + 2 * i;
  float2 tq = *(float2*)&q[base];
  float2 tk = *(float2*)&k[base];
  float2 oq, ok;
  oq.x = tq.x * c0 - tq.y * s0;
  oq.y = tq.y * c1 + tq.x * s1;
  ok.x = tk.x * c0 - tk.y * s0;
  ok.y = tk.y * c1 + tk.x * s1;
  *(float2*)&q[base] = oq;
  *(float2*)&k[base] = ok;
}

// ---------------------------------------------------------------------------
// Flash attention with TF32 tensor cores + ldmatrix fragment loads.
// Layouts unchanged from the passing R5 kernel (FS=68 is LDSM-conflict-free).
// ---------------------------------------------------------------------------
#define FS 68
#define FA_SMEM_WORDS (128 * FS + 64 * FS + 64 * FS + 128 * FS)
#define FA_SMEM_BYTES (FA_SMEM_WORDS * 4)

__global__ __launch_bounds__(256) void flash_attn_tc(
    const float* __restrict__ gq, const float* __restrict__ gk,
    const float* __restrict__ gv, float* __restrict__ gctx) {
  extern __shared__ uint32_t usm[];
  uint32_t* Qs = usm;               // [128][FS]  Qs[row][d]
  uint32_t* Ks = Qs + 128 * FS;     // [64][FS]   Ks[tok][d]
  uint32_t* Vs = Ks + 64 * FS;      // [64][FS]   Vs[d][tok]
  uint32_t* Ps = Vs + 64 * FS;      // [128][FS]  Ps[row][kv]

  const int tid = threadIdx.x;
  const int warp = tid >> 5, lane = tid & 31;
  const int g = lane >> 2, tc = lane & 3;
  const int qt = blockIdx.x, h = blockIdx.y, b = blockIdx.z;
  const int qrow0 = b * LL + qt * 128;
  const int hoff = h * KK;
  const int wrow = warp * 16;

  // ldmatrix per-lane byte offsets
  const uint32_t a_lnoff = ((wrow + (lane & 15)) * FS + 4 * (lane >> 4)) * 4;
  const uint32_t b_lnoff =
      ((8 * (lane >> 4) + (lane & 7)) * FS + 4 * ((lane >> 3) & 1)) * 4;
  const uint32_t qs_u = s2u(Qs), ks_u = s2u(Ks), vs_u = s2u(Vs), ps_u = s2u(Ps);

  // Load Q tile, pre-scaled by 1/sqrt(64)=0.125
  {
    int r = tid >> 1;
    int d0 = (tid & 1) * 32;
    const float* src = gq + (size_t)(qrow0 + r) * DD + hoff + d0;
    uint32_t* dst = &Qs[r * FS + d0];
    #pragma unroll
    for (int u = 0; u < 8; u++) {
      float4 x = *(const float4*)(src + 4 * u);
      dst[4 * u + 0] = f2tf32(0.125f * x.x);
      dst[4 * u + 1] = f2tf32(0.125f * x.y);
      dst[4 * u + 2] = f2tf32(0.125f * x.z);
      dst[4 * u + 3] = f2tf32(0.125f * x.w);
    }
  }

  float o[8][4];
  #pragma unroll
  for (int ni = 0; ni < 8; ni++)
    #pragma unroll
    for (int r = 0; r < 4; r++) o[ni][r] = 0.0f;
  float mrow0 = -1e30f, mrow1 = -1e30f;
  float lrow0 = 0.0f, lrow1 = 0.0f;

  for (int t = 0; t < LL / 64; t++) {
    // Load K [tok][d] and V transposed [d][tok]
    {
      int kbase = b * LL + t * 64;
      int tok = tid >> 2;
      int d0 = (tid & 3) * 16;
      const float* ks = gk + (size_t)(kbase + tok) * DD + hoff + d0;
      const float* vs = gv + (size_t)(kbase + tok) * DD + hoff + d0;
      #pragma unroll
      for (int u = 0; u < 4; u++) {
        float4 x = *(const float4*)(ks + 4 * u);
        uint32_t* kd = &Ks[tok * FS + d0 + 4 * u];
        kd[0] = f2tf32(x.x); kd[1] = f2tf32(x.y);
        kd[2] = f2tf32(x.z); kd[3] = f2tf32(x.w);
        float4 y = *(const float4*)(vs + 4 * u);
        Vs[(d0 + 4 * u + 0) * FS + tok] = f2tf32(y.x);
        Vs[(d0 + 4 * u + 1) * FS + tok] = f2tf32(y.y);
        Vs[(d0 + 4 * u + 2) * FS + tok] = f2tf32(y.z);
        Vs[(d0 + 4 * u + 3) * FS + tok] = f2tf32(y.w);
      }
    }
    __syncthreads();

    // S = Q K^T
    float sacc[8][4];
    #pragma unroll
    for (int ni = 0; ni < 8; ni++)
      #pragma unroll
      for (int r = 0; r < 4; r++) sacc[ni][r] = 0.0f;

    #pragma unroll
    for (int ks = 0; ks < 8; ks++) {
      uint32_t a[4];
      ldsm_x4(a, qs_u + a_lnoff + ks * 32);
      #pragma unroll
      for (int ni = 0; ni < 8; ni += 2) {
        uint32_t bq[4];
        ldsm_x4(bq, ks_u + b_lnoff + (uint32_t)(ni * 8 * FS * 4) + ks * 32);
        mma_tf32(sacc[ni], a, bq[0], bq[1]);
        mma_tf32(sacc[ni + 1], a, bq[2], bq[3]);
      }
    }

    // Warp-local online softmax
    float mx0 = -1e30f, mx1 = -1e30f;
    #pragma unroll
    for (int ni = 0; ni < 8; ni++) {
      mx0 = fmaxf(mx0, fmaxf(sacc[ni][0], sacc[ni][1]));
      mx1 = fmaxf(mx1, fmaxf(sacc[ni][2], sacc[ni][3]));
    }
    mx0 = fmaxf(mx0, __shfl_xor_sync(0xffffffffu, mx0, 1));
    mx0 = fmaxf(mx0, __shfl_xor_sync(0xffffffffu, mx0, 2));
    mx1 = fmaxf(mx1, __shfl_xor_sync(0xffffffffu, mx1, 1));
    mx1 = fmaxf(mx1, __shfl_xor_sync(0xffffffffu, mx1, 2));

    float mn0 = fmaxf(mrow0, mx0);
    float mn1 = fmaxf(mrow1, mx1);
    float corr0 = __expf(mrow0 - mn0);
    float corr1 = __expf(mrow1 - mn1);
    mrow0 = mn0; mrow1 = mn1;

    float ls0 = 0.0f, ls1 = 0.0f;
    #pragma unroll
    for (int ni = 0; ni < 8; ni++) {
      float p00 = __expf(sacc[ni][0] - mn0);
      float p01 = __expf(sacc[ni][1] - mn0);
      float p10 = __expf(sacc[ni][2] - mn1);
      float p11 = __expf(sacc[ni][3] - mn1);
      ls0 += p00 + p01;
      ls1 += p10 + p11;
      int col = ni * 8 + 2 * tc;
      uint32_t* p0 = &Ps[(wrow + g) * FS + col];
      p0[0] = f2tf32(p00); p0[1] = f2tf32(p01);
      uint32_t* p1 = &Ps[(wrow + g + 8) * FS + col];
      p1[0] = f2tf32(p10); p1[1] = f2tf32(p11);
    }
    ls0 += __shfl_xor_sync(0xffffffffu, ls0, 1);
    ls0 += __shfl_xor_sync(0xffffffffu, ls0, 2);
    ls1 += __shfl_xor_sync(0xffffffffu, ls1, 1);
    ls1 += __shfl_xor_sync(0xffffffffu, ls1, 2);
    lrow0 = lrow0 * corr0 + ls0;
    lrow1 = lrow1 * corr1 + ls1;

    #pragma unroll
    for (int ni = 0; ni < 8; ni++) {
      o[ni][0] *= corr0; o[ni][1] *= corr0;
      o[ni][2] *= corr1; o[ni][3] *= corr1;
    }
    __syncwarp();

    // O += P @ V
    #pragma unroll
    for (int ks = 0; ks < 8; ks++) {
      uint32_t a[4];
      ldsm_x4(a, ps_u + a_lnoff + ks * 32);
      #pragma unroll
      for (int ni = 0; ni < 8; ni += 2) {
        uint32_t bv[4];
        ldsm_x4(bv, vs_u + b_lnoff + (uint32_t)(ni * 8 * FS * 4) + ks * 32);
        mma_tf32(o[ni], a, bv[0], bv[1]);
        mma_tf32(o[ni + 1], a, bv[2], bv[3]);
      }
    }
    __syncthreads();
  }

  // Normalize and store
  float inv0 = 1.0f / lrow0;
  float inv1 = 1.0f / lrow1;
  #pragma unroll
  for (int ni = 0; ni < 8; ni++) {
    int col = hoff + ni * 8 + 2 * tc;
    int row0 = qrow0 + wrow + g;
    *(float2*)&gctx[(size_t)row0 * DD + col] =
        make_float2(o[ni][0] * inv0, o[ni][1] * inv0);
    *(float2*)&gctx[(size_t)(row0 + 8) * DD + col] =
        make_float2(o[ni][2] * inv1, o[ni][3] * inv1);
  }
}

// ---------------------------------------------------------------------------
extern "C" void kernel_launch(void* const* d_in, const int* in_sizes, int n_in,
                              void* d_out, int out_size) {
  const float* query    = (const float*)d_in[0];
  const float* key      = (const float*)d_in[1];
  const float* value    = (const float*)d_in[2];
  const float* rot      = (const float*)d_in[3];
  const float* q_kernel = (const float*)d_in[4];
  const float* k_kernel = (const float*)d_in[5];
  const float* v_kernel = (const float*)d_in[6];
  const float* o_kernel = (const float*)d_in[7];
  float* out = (float*)d_out;

  float *pq, *pk, *pv, *pctx;
  cudaGetSymbolAddress((void**)&pq, g_q);
  cudaGetSymbolAddress((void**)&pk, g_k);
  cudaGetSymbolAddress((void**)&pv, g_v);
  cudaGetSymbolAddress((void**)&pctx, g_ctx);

  // QKV projections fused into one launch (grid.z selects A/B/C)
  sgemm_tf32_db<<<dim3(DD / 128, MROWS / 128, 3), 256>>>(
      query, key, value, q_kernel, k_kernel, v_kernel, pq, pk, pv,
      MROWS, DD, DD);

  // RoPE on q, k
  {
    int total = MROWS * HH * (ROT / 2);
    rope_kernel<<<(total + 255) / 256, 256>>>(pq, pk, rot);
  }

  // Flash attention (tf32 tensor cores + ldmatrix)
  cudaFuncSetAttribute(flash_attn_tc, cudaFuncAttributeMaxDynamicSharedMemorySize,
                       FA_SMEM_BYTES);
  flash_attn_tc<<<dim3(LL / 128, HH, BB), 256, FA_SMEM_BYTES>>>(pq, pk, pv, pctx);

  // Output projection
  sgemm_tf32_db<<<dim3(DD / 128, MROWS / 128, 1), 256>>>(
      pctx, pctx, pctx, o_kernel, o_kernel, o_kernel, out, out, out,
      MROWS, DD, DD);
}

// round 10
// speedup vs baseline: 2.8709x; 1.0676x over previous
#include <cuda_runtime.h>
#include <math.h>
#include <stdint.h>

// Problem constants
#define BB 2
#define LL 2048
#define DD 1024
#define HH 16
#define KK 64
#define ROT 32
#define MROWS (BB * LL)   // 4096

// Scratch (static device arrays: allocation-free)
__device__ float g_q[MROWS * DD];
__device__ float g_k[MROWS * DD];
__device__ float g_v[MROWS * DD];
__device__ float g_ctx[MROWS * DD];

__device__ __forceinline__ uint32_t f2tf32(float f) {
  uint32_t u;
  asm("cvt.rna.tf32.f32 %0, %1;" : "=r"(u) : "f"(f));
  return u;
}

__device__ __forceinline__ void mma_tf32(float c[4], const uint32_t a[4],
                                         uint32_t b0, uint32_t b1) {
  asm("mma.sync.aligned.m16n8k8.row.col.f32.tf32.tf32.f32 "
      "{%0,%1,%2,%3},{%4,%5,%6,%7},{%8,%9},{%0,%1,%2,%3};"
      : "+f"(c[0]), "+f"(c[1]), "+f"(c[2]), "+f"(c[3])
      : "r"(a[0]), "r"(a[1]), "r"(a[2]), "r"(a[3]), "r"(b0), "r"(b1));
}

__device__ __forceinline__ void ldsm_x4(uint32_t* r, uint32_t addr) {
  asm volatile("ldmatrix.sync.aligned.m8n8.x4.shared.b16 {%0,%1,%2,%3}, [%4];"
               : "=r"(r[0]), "=r"(r[1]), "=r"(r[2]), "=r"(r[3]) : "r"(addr));
}

__device__ __forceinline__ uint32_t s2u(const void* p) {
  return (uint32_t)__cvta_generic_to_shared(p);
}

// ---------------------------------------------------------------------------
// TF32 tensor-core GEMM, double-buffered, ldmatrix for BOTH operands.
// C[M,N] = A[M,Kd] * B[Kd,N], row-major. Block 128x128, BK=16, 256 threads,
// 8 warps (4m x 2n), warp tile 32x64.
// A smem: [m][16 k-words], chunk swizzle c^((m>>1)&3).
// B smem: [n][16 k-words], chunk swizzle c^((n>>1)&3)  (NEW: was [k][n] scalar).
// Both: conflict-free STS.128 producers + ldmatrix.x4 consumers.
// ---------------------------------------------------------------------------
#define AK 16

__global__ __launch_bounds__(256, 2) void sgemm_tf32_db(
    const float* __restrict__ A0, const float* __restrict__ A1,
    const float* __restrict__ A2, const float* __restrict__ B0,
    const float* __restrict__ B1, const float* __restrict__ B2,
    float* __restrict__ C0, float* __restrict__ C1, float* __restrict__ C2,
    int M, int N, int Kd) {
  __shared__ uint32_t As[2][128 * AK];
  __shared__ uint32_t Bs[2][128 * AK];

  const int z = blockIdx.z;
  const float* A = (z == 0) ? A0 : (z == 1) ? A1 : A2;
  const float* B = (z == 0) ? B0 : (z == 1) ? B1 : B2;
  float* C = (z == 0) ? C0 : (z == 1) ? C1 : C2;

  const int tid = threadIdx.x;
  const int warp = tid >> 5, lane = tid & 31;
  const int g = lane >> 2, tc = lane & 3;
  const int wm = warp & 3, wn = warp >> 2;
  const int m_base = wm * 32;
  const int n_base = wn * 64;
  const int crow = blockIdx.y * 128;
  const int ccol = blockIdx.x * 128;

  // A producer: thread -> rows (pr, pr+64), chunk pc (coalesced LDG.128)
  const int pr = tid >> 2;         // 0..63
  const int pc = tid & 3;          // chunk 0..3
  const int psw = (pr >> 1) & 3;   // same for pr and pr+64
  const uint32_t pd0 = pr * AK + 4 * (pc ^ psw);
  const uint32_t pd1 = (pr + 64) * AK + 4 * (pc ^ psw);
  const float* Ap0 = A + (size_t)(crow + pr) * Kd + pc * 4;
  const float* Ap1 = Ap0 + (size_t)64 * Kd;

  // B producer: thread -> n = tid&127, k-half = tid>>7; 8 coalesced LDG.32
  const int bn = tid & 127;
  const int bhalf = tid >> 7;          // 0 or 1 -> k 0..7 or 8..15
  const int bsw = (bn >> 1) & 3;
  const uint32_t bd0 = bn * AK + 4 * ((2 * bhalf) ^ bsw);
  const uint32_t bd1 = bn * AK + 4 * ((2 * bhalf + 1) ^ bsw);
  const float* Bp = B + (size_t)(8 * bhalf) * N + ccol + bn;

  // A consumer (ldmatrix)
  const int a_ln = m_base + (lane & 15);
  const int a_sw = (a_ln >> 1) & 3;
  const int a_hi = lane >> 4;

  // B consumer (ldmatrix): lane -> matrix j = lane>>3, row r = lane&7
  const int b_j = lane >> 3;
  const int b_nrow_off = (b_j >> 1) * 8 + (lane & 7);   // 0..15 within ni-pair
  const int b_cbit = b_j & 1;                           // chunk low bit
  const int b_sw = (b_nrow_off >> 1) & 3;               // lane-constant swizzle
  const uint32_t b_base_off = (uint32_t)(n_base + b_nrow_off) * AK * 4;

  float acc[2][8][4];
  #pragma unroll
  for (int mi = 0; mi < 2; mi++)
    #pragma unroll
    for (int ni = 0; ni < 8; ni++)
      #pragma unroll
      for (int r = 0; r < 4; r++) acc[mi][ni][r] = 0.0f;

  // Prologue: tile 0 -> buffer 0
  float4 xa0 = *(const float4*)Ap0;
  float4 xa1 = *(const float4*)Ap1;
  float bw[8];
  #pragma unroll
  for (int i = 0; i < 8; i++) bw[i] = Bp[(size_t)i * N];
  Ap0 += 16; Ap1 += 16;
  Bp += (size_t)16 * N;
  {
    uint32_t* as = As[0];
    *(uint4*)&as[pd0] = make_uint4(f2tf32(xa0.x), f2tf32(xa0.y), f2tf32(xa0.z), f2tf32(xa0.w));
    *(uint4*)&as[pd1] = make_uint4(f2tf32(xa1.x), f2tf32(xa1.y), f2tf32(xa1.z), f2tf32(xa1.w));
    uint32_t* bs = Bs[0];
    *(uint4*)&bs[bd0] = make_uint4(f2tf32(bw[0]), f2tf32(bw[1]), f2tf32(bw[2]), f2tf32(bw[3]));
    *(uint4*)&bs[bd1] = make_uint4(f2tf32(bw[4]), f2tf32(bw[5]), f2tf32(bw[6]), f2tf32(bw[7]));
  }
  __syncthreads();

  const uint32_t as_u[2] = {s2u(As[0]), s2u(As[1])};
  const uint32_t bs_u[2] = {s2u(Bs[0]), s2u(Bs[1])};

  int buf = 0;
  const int iters = Kd / 16;
  for (int it = 0; it < iters; it++) {
    const bool last = (it == iters - 1);
    if (!last) {
      xa0 = *(const float4*)Ap0;
      xa1 = *(const float4*)Ap1;
      #pragma unroll
      for (int i = 0; i < 8; i++) bw[i] = Bp[(size_t)i * N];
      Ap0 += 16; Ap1 += 16;
      Bp += (size_t)16 * N;
    }

    const uint32_t au = as_u[buf];
    const uint32_t bu = bs_u[buf] + b_base_off;
    #pragma unroll
    for (int ksi = 0; ksi < 2; ksi++) {
      uint32_t afr[2][4];
      #pragma unroll
      for (int mi = 0; mi < 2; mi++) {
        uint32_t addr = au + (uint32_t)(a_ln + mi * 16) * 64 +
                        16u * (uint32_t)((2 * ksi + a_hi) ^ a_sw);
        ldsm_x4(afr[mi], addr);
      }
      const uint32_t b_koff = 16u * (uint32_t)((2 * ksi + b_cbit) ^ b_sw);
      #pragma unroll
      for (int nip = 0; nip < 8; nip += 2) {
        uint32_t bq[4];
        ldsm_x4(bq, bu + (uint32_t)(nip * 8 * AK * 4) + b_koff);
        mma_tf32(acc[0][nip],     afr[0], bq[0], bq[1]);
        mma_tf32(acc[0][nip + 1], afr[0], bq[2], bq[3]);
        mma_tf32(acc[1][nip],     afr[1], bq[0], bq[1]);
        mma_tf32(acc[1][nip + 1], afr[1], bq[2], bq[3]);
      }
    }

    if (!last) {
      uint32_t* as = As[buf ^ 1];
      *(uint4*)&as[pd0] = make_uint4(f2tf32(xa0.x), f2tf32(xa0.y), f2tf32(xa0.z), f2tf32(xa0.w));
      *(uint4*)&as[pd1] = make_uint4(f2tf32(xa1.x), f2tf32(xa1.y), f2tf32(xa1.z), f2tf32(xa1.w));
      uint32_t* bs = Bs[buf ^ 1];
      *(uint4*)&bs[bd0] = make_uint4(f2tf32(bw[0]), f2tf32(bw[1]), f2tf32(bw[2]), f2tf32(bw[3]));
      *(uint4*)&bs[bd1] = make_uint4(f2tf32(bw[4]), f2tf32(bw[5]), f2tf32(bw[6]), f2tf32(bw[7]));
      __syncthreads();
      buf ^= 1;
    }
  }

  #pragma unroll
  for (int mi = 0; mi < 2; mi++) {
    #pragma unroll
    for (int ni = 0; ni < 8; ni++) {
      int row = crow + m_base + mi * 16 + g;
      int col = ccol + n_base + ni * 8 + 2 * tc;
      *(float2*)&C[(size_t)row * N + col] =
          make_float2(acc[mi][ni][0], acc[mi][ni][1]);
      *(float2*)&C[(size_t)(row + 8) * N + col] =
          make_float2(acc[mi][ni][2], acc[mi][ni][3]);
    }
  }
}

// ---------------------------------------------------------------------------
// RoPE applied in-place to q and k (first ROT dims of each head)
// ---------------------------------------------------------------------------
__global__ void rope_kernel(float* __restrict__ q, float* __restrict__ k,
                            const float* __restrict__ rot) {
  int idx = blockIdx.x * 256 + threadIdx.x;
  const int total = MROWS * HH * (ROT / 2);
  if (idx >= total) return;
  int i = idx & 15;
  int h = (idx >> 4) & 15;
  int row = idx >> 8;
  int l = row & (LL - 1);

  float f0 = rot[l * ROT + 2 * i];
  float f1 = rot[l * ROT + 2 * i + 1];
  float s0, c0, s1, c1;
  sincosf(f0, &s0, &c0);
  sincosf(f1, &s1, &c1);

  int base = row * DD + h * KK + 2 * i;
  float2 tq = *(float2*)&q[base];
  float2 tk = *(float2*)&k[base];
  float2 oq, ok;
  oq.x = tq.x * c0 - tq.y * s0;
  oq.y = tq.y * c1 + tq.x * s1;
  ok.x = tk.x * c0 - tk.y * s0;
  ok.y = tk.y * c1 + tk.x * s1;
  *(float2*)&q[base] = oq;
  *(float2*)&k[base] = ok;
}

// ---------------------------------------------------------------------------
// Flash attention with TF32 tensor cores + ldmatrix fragment loads.
// (Unchanged from R9 passing version.)
// ---------------------------------------------------------------------------
#define FS 68
#define FA_SMEM_WORDS (128 * FS + 64 * FS + 64 * FS + 128 * FS)
#define FA_SMEM_BYTES (FA_SMEM_WORDS * 4)

__global__ __launch_bounds__(256) void flash_attn_tc(
    const float* __restrict__ gq, const float* __restrict__ gk,
    const float* __restrict__ gv, float* __restrict__ gctx) {
  extern __shared__ uint32_t usm[];
  uint32_t* Qs = usm;               // [128][FS]  Qs[row][d]
  uint32_t* Ks = Qs + 128 * FS;     // [64][FS]   Ks[tok][d]
  uint32_t* Vs = Ks + 64 * FS;      // [64][FS]   Vs[d][tok]
  uint32_t* Ps = Vs + 64 * FS;      // [128][FS]  Ps[row][kv]

  const int tid = threadIdx.x;
  const int warp = tid >> 5, lane = tid & 31;
  const int g = lane >> 2, tc = lane & 3;
  const int qt = blockIdx.x, h = blockIdx.y, b = blockIdx.z;
  const int qrow0 = b * LL + qt * 128;
  const int hoff = h * KK;
  const int wrow = warp * 16;

  // ldmatrix per-lane byte offsets
  const uint32_t a_lnoff = ((wrow + (lane & 15)) * FS + 4 * (lane >> 4)) * 4;
  const uint32_t b_lnoff =
      ((8 * (lane >> 4) + (lane & 7)) * FS + 4 * ((lane >> 3) & 1)) * 4;
  const uint32_t qs_u = s2u(Qs), ks_u = s2u(Ks), vs_u = s2u(Vs), ps_u = s2u(Ps);

  // Load Q tile, pre-scaled by 1/sqrt(64)=0.125
  {
    int r = tid >> 1;
    int d0 = (tid & 1) * 32;
    const float* src = gq + (size_t)(qrow0 + r) * DD + hoff + d0;
    uint32_t* dst = &Qs[r * FS + d0];
    #pragma unroll
    for (int u = 0; u < 8; u++) {
      float4 x = *(const float4*)(src + 4 * u);
      dst[4 * u + 0] = f2tf32(0.125f * x.x);
      dst[4 * u + 1] = f2tf32(0.125f * x.y);
      dst[4 * u + 2] = f2tf32(0.125f * x.z);
      dst[4 * u + 3] = f2tf32(0.125f * x.w);
    }
  }

  float o[8][4];
  #pragma unroll
  for (int ni = 0; ni < 8; ni++)
    #pragma unroll
    for (int r = 0; r < 4; r++) o[ni][r] = 0.0f;
  float mrow0 = -1e30f, mrow1 = -1e30f;
  float lrow0 = 0.0f, lrow1 = 0.0f;

  for (int t = 0; t < LL / 64; t++) {
    // Load K [tok][d] and V transposed [d][tok]
    {
      int kbase = b * LL + t * 64;
      int tok = tid >> 2;
      int d0 = (tid & 3) * 16;
      const float* ks = gk + (size_t)(kbase + tok) * DD + hoff + d0;
      const float* vs = gv + (size_t)(kbase + tok) * DD + hoff + d0;
      #pragma unroll
      for (int u = 0; u < 4; u++) {
        float4 x = *(const float4*)(ks + 4 * u);
        uint32_t* kd = &Ks[tok * FS + d0 + 4 * u];
        kd[0] = f2tf32(x.x); kd[1] = f2tf32(x.y);
        kd[2] = f2tf32(x.z); kd[3] = f2tf32(x.w);
        float4 y = *(const float4*)(vs + 4 * u);
        Vs[(d0 + 4 * u + 0) * FS + tok] = f2tf32(y.x);
        Vs[(d0 + 4 * u + 1) * FS + tok] = f2tf32(y.y);
        Vs[(d0 + 4 * u + 2) * FS + tok] = f2tf32(y.z);
        Vs[(d0 + 4 * u + 3) * FS + tok] = f2tf32(y.w);
      }
    }
    __syncthreads();

    // S = Q K^T
    float sacc[8][4];
    #pragma unroll
    for (int ni = 0; ni < 8; ni++)
      #pragma unroll
      for (int r = 0; r < 4; r++) sacc[ni][r] = 0.0f;

    #pragma unroll
    for (int ks = 0; ks < 8; ks++) {
      uint32_t a[4];
      ldsm_x4(a, qs_u + a_lnoff + ks * 32);
      #pragma unroll
      for (int ni = 0; ni < 8; ni += 2) {
        uint32_t bq[4];
        ldsm_x4(bq, ks_u + b_lnoff + (uint32_t)(ni * 8 * FS * 4) + ks * 32);
        mma_tf32(sacc[ni], a, bq[0], bq[1]);
        mma_tf32(sacc[ni + 1], a, bq[2], bq[3]);
      }
    }

    // Warp-local online softmax
    float mx0 = -1e30f, mx1 = -1e30f;
    #pragma unroll
    for (int ni = 0; ni < 8; ni++) {
      mx0 = fmaxf(mx0, fmaxf(sacc[ni][0], sacc[ni][1]));
      mx1 = fmaxf(mx1, fmaxf(sacc[ni][2], sacc[ni][3]));
    }
    mx0 = fmaxf(mx0, __shfl_xor_sync(0xffffffffu, mx0, 1));
    mx0 = fmaxf(mx0, __shfl_xor_sync(0xffffffffu, mx0, 2));
    mx1 = fmaxf(mx1, __shfl_xor_sync(0xffffffffu, mx1, 1));
    mx1 = fmaxf(mx1, __shfl_xor_sync(0xffffffffu, mx1, 2));

    float mn0 = fmaxf(mrow0, mx0);
    float mn1 = fmaxf(mrow1, mx1);
    float corr0 = __expf(mrow0 - mn0);
    float corr1 = __expf(mrow1 - mn1);
    mrow0 = mn0; mrow1 = mn1;

    float ls0 = 0.0f, ls1 = 0.0f;
    #pragma unroll
    for (int ni = 0; ni < 8; ni++) {
      float p00 = __expf(sacc[ni][0] - mn0);
      float p01 = __expf(sacc[ni][1] - mn0);
      float p10 = __expf(sacc[ni][2] - mn1);
      float p11 = __expf(sacc[ni][3] - mn1);
      ls0 += p00 + p01;
      ls1 += p10 + p11;
      int col = ni * 8 + 2 * tc;
      uint32_t* p0 = &Ps[(wrow + g) * FS + col];
      p0[0] = f2tf32(p00); p0[1] = f2tf32(p01);
      uint32_t* p1 = &Ps[(wrow + g + 8) * FS + col];
      p1[0] = f2tf32(p10); p1[1] = f2tf32(p11);
    }
    ls0 += __shfl_xor_sync(0xffffffffu, ls0, 1);
    ls0 += __shfl_xor_sync(0xffffffffu, ls0, 2);
    ls1 += __shfl_xor_sync(0xffffffffu, ls1, 1);
    ls1 += __shfl_xor_sync(0xffffffffu, ls1, 2);
    lrow0 = lrow0 * corr0 + ls0;
    lrow1 = lrow1 * corr1 + ls1;

    #pragma unroll
    for (int ni = 0; ni < 8; ni++) {
      o[ni][0] *= corr0; o[ni][1] *= corr0;
      o[ni][2] *= corr1; o[ni][3] *= corr1;
    }
    __syncwarp();

    // O += P @ V
    #pragma unroll
    for (int ks = 0; ks < 8; ks++) {
      uint32_t a[4];
      ldsm_x4(a, ps_u + a_lnoff + ks * 32);
      #pragma unroll
      for (int ni = 0; ni < 8; ni += 2) {
        uint32_t bv[4];
        ldsm_x4(bv, vs_u + b_lnoff + (uint32_t)(ni * 8 * FS * 4) + ks * 32);
        mma_tf32(o[ni], a, bv[0], bv[1]);
        mma_tf32(o[ni + 1], a, bv[2], bv[3]);
      }
    }
    __syncthreads();
  }

  // Normalize and store
  float inv0 = 1.0f / lrow0;
  float inv1 = 1.0f / lrow1;
  #pragma unroll
  for (int ni = 0; ni < 8; ni++) {
    int col = hoff + ni * 8 + 2 * tc;
    int row0 = qrow0 + wrow + g;
    *(float2*)&gctx[(size_t)row0 * DD + col] =
        make_float2(o[ni][0] * inv0, o[ni][1] * inv0);
    *(float2*)&gctx[(size_t)(row0 + 8) * DD + col] =
        make_float2(o[ni][2] * inv1, o[ni][3] * inv1);
  }
}

// ---------------------------------------------------------------------------
extern "C" void kernel_launch(void* const* d_in, const int* in_sizes, int n_in,
                              void* d_out, int out_size) {
  const float* query    = (const float*)d_in[0];
  const float* key      = (const float*)d_in[1];
  const float* value    = (const float*)d_in[2];
  const float* rot      = (const float*)d_in[3];
  const float* q_kernel = (const float*)d_in[4];
  const float* k_kernel = (const float*)d_in[5];
  const float* v_kernel = (const float*)d_in[6];
  const float* o_kernel = (const float*)d_in[7];
  float* out = (float*)d_out;

  float *pq, *pk, *pv, *pctx;
  cudaGetSymbolAddress((void**)&pq, g_q);
  cudaGetSymbolAddress((void**)&pk, g_k);
  cudaGetSymbolAddress((void**)&pv, g_v);
  cudaGetSymbolAddress((void**)&pctx, g_ctx);

  // QKV projections fused into one launch (grid.z selects A/B/C)
  sgemm_tf32_db<<<dim3(DD / 128, MROWS / 128, 3), 256>>>(
      query, key, value, q_kernel, k_kernel, v_kernel, pq, pk, pv,
      MROWS, DD, DD);

  // RoPE on q, k
  {
    int total = MROWS * HH * (ROT / 2);
    rope_kernel<<<(total + 255) / 256, 256>>>(pq, pk, rot);
  }

  // Flash attention (tf32 tensor cores + ldmatrix)
  cudaFuncSetAttribute(flash_attn_tc, cudaFuncAttributeMaxDynamicSharedMemorySize,
                       FA_SMEM_BYTES);
  flash_attn_tc<<<dim3(LL / 128, HH, BB), 256, FA_SMEM_BYTES>>>(pq, pk, pv, pctx);

  // Output projection
  sgemm_tf32_db<<<dim3(DD / 128, MROWS / 128, 1), 256>>>(
      pctx, pctx, pctx, o_kernel, o_kernel, o_kernel, out, out, out,
      MROWS, DD, DD);
}

// round 11
// speedup vs baseline: 3.0275x; 1.0546x over previous
#include <cuda_runtime.h>
#include <math.h>
#include <stdint.h>

// Problem constants
#define BB 2
#define LL 2048
#define DD 1024
#define HH 16
#define KK 64
#define ROT 32
#define MROWS (BB * LL)   // 4096

// Scratch (static device arrays: allocation-free)
__device__ float g_q[MROWS * DD];
__device__ float g_k[MROWS * DD];
__device__ float g_v[MROWS * DD];
__device__ float g_ctx[MROWS * DD];

__device__ __forceinline__ uint32_t f2tf32(float f) {
  uint32_t u;
  asm("cvt.rna.tf32.f32 %0, %1;" : "=r"(u) : "f"(f));
  return u;
}

__device__ __forceinline__ void mma_tf32(float c[4], const uint32_t a[4],
                                         uint32_t b0, uint32_t b1) {
  asm("mma.sync.aligned.m16n8k8.row.col.f32.tf32.tf32.f32 "
      "{%0,%1,%2,%3},{%4,%5,%6,%7},{%8,%9},{%0,%1,%2,%3};"
      : "+f"(c[0]), "+f"(c[1]), "+f"(c[2]), "+f"(c[3])
      : "r"(a[0]), "r"(a[1]), "r"(a[2]), "r"(a[3]), "r"(b0), "r"(b1));
}

__device__ __forceinline__ void ldsm_x4(uint32_t* r, uint32_t addr) {
  asm volatile("ldmatrix.sync.aligned.m8n8.x4.shared.b16 {%0,%1,%2,%3}, [%4];"
               : "=r"(r[0]), "=r"(r[1]), "=r"(r[2]), "=r"(r[3]) : "r"(addr));
}

__device__ __forceinline__ uint32_t s2u(const void* p) {
  return (uint32_t)__cvta_generic_to_shared(p);
}

// ---------------------------------------------------------------------------
// TF32 tensor-core GEMM, double-buffered, ldmatrix for BOTH operands.
// (Unchanged from R10 passing version.)
// ---------------------------------------------------------------------------
#define AK 16

__global__ __launch_bounds__(256, 2) void sgemm_tf32_db(
    const float* __restrict__ A0, const float* __restrict__ A1,
    const float* __restrict__ A2, const float* __restrict__ B0,
    const float* __restrict__ B1, const float* __restrict__ B2,
    float* __restrict__ C0, float* __restrict__ C1, float* __restrict__ C2,
    int M, int N, int Kd) {
  __shared__ uint32_t As[2][128 * AK];
  __shared__ uint32_t Bs[2][128 * AK];

  const int z = blockIdx.z;
  const float* A = (z == 0) ? A0 : (z == 1) ? A1 : A2;
  const float* B = (z == 0) ? B0 : (z == 1) ? B1 : B2;
  float* C = (z == 0) ? C0 : (z == 1) ? C1 : C2;

  const int tid = threadIdx.x;
  const int warp = tid >> 5, lane = tid & 31;
  const int g = lane >> 2, tc = lane & 3;
  const int wm = warp & 3, wn = warp >> 2;
  const int m_base = wm * 32;
  const int n_base = wn * 64;
  const int crow = blockIdx.y * 128;
  const int ccol = blockIdx.x * 128;

  const int pr = tid >> 2;
  const int pc = tid & 3;
  const int psw = (pr >> 1) & 3;
  const uint32_t pd0 = pr * AK + 4 * (pc ^ psw);
  const uint32_t pd1 = (pr + 64) * AK + 4 * (pc ^ psw);
  const float* Ap0 = A + (size_t)(crow + pr) * Kd + pc * 4;
  const float* Ap1 = Ap0 + (size_t)64 * Kd;

  const int bn = tid & 127;
  const int bhalf = tid >> 7;
  const int bsw = (bn >> 1) & 3;
  const uint32_t bd0 = bn * AK + 4 * ((2 * bhalf) ^ bsw);
  const uint32_t bd1 = bn * AK + 4 * ((2 * bhalf + 1) ^ bsw);
  const float* Bp = B + (size_t)(8 * bhalf) * N + ccol + bn;

  const int a_ln = m_base + (lane & 15);
  const int a_sw = (a_ln >> 1) & 3;
  const int a_hi = lane >> 4;

  const int b_j = lane >> 3;
  const int b_nrow_off = (b_j >> 1) * 8 + (lane & 7);
  const int b_cbit = b_j & 1;
  const int b_sw = (b_nrow_off >> 1) & 3;
  const uint32_t b_base_off = (uint32_t)(n_base + b_nrow_off) * AK * 4;

  float acc[2][8][4];
  #pragma unroll
  for (int mi = 0; mi < 2; mi++)
    #pragma unroll
    for (int ni = 0; ni < 8; ni++)
      #pragma unroll
      for (int r = 0; r < 4; r++) acc[mi][ni][r] = 0.0f;

  float4 xa0 = *(const float4*)Ap0;
  float4 xa1 = *(const float4*)Ap1;
  float bw[8];
  #pragma unroll
  for (int i = 0; i < 8; i++) bw[i] = Bp[(size_t)i * N];
  Ap0 += 16; Ap1 += 16;
  Bp += (size_t)16 * N;
  {
    uint32_t* as = As[0];
    *(uint4*)&as[pd0] = make_uint4(f2tf32(xa0.x), f2tf32(xa0.y), f2tf32(xa0.z), f2tf32(xa0.w));
    *(uint4*)&as[pd1] = make_uint4(f2tf32(xa1.x), f2tf32(xa1.y), f2tf32(xa1.z), f2tf32(xa1.w));
    uint32_t* bs = Bs[0];
    *(uint4*)&bs[bd0] = make_uint4(f2tf32(bw[0]), f2tf32(bw[1]), f2tf32(bw[2]), f2tf32(bw[3]));
    *(uint4*)&bs[bd1] = make_uint4(f2tf32(bw[4]), f2tf32(bw[5]), f2tf32(bw[6]), f2tf32(bw[7]));
  }
  __syncthreads();

  const uint32_t as_u[2] = {s2u(As[0]), s2u(As[1])};
  const uint32_t bs_u[2] = {s2u(Bs[0]), s2u(Bs[1])};

  int buf = 0;
  const int iters = Kd / 16;
  for (int it = 0; it < iters; it++) {
    const bool last = (it == iters - 1);
    if (!last) {
      xa0 = *(const float4*)Ap0;
      xa1 = *(const float4*)Ap1;
      #pragma unroll
      for (int i = 0; i < 8; i++) bw[i] = Bp[(size_t)i * N];
      Ap0 += 16; Ap1 += 16;
      Bp += (size_t)16 * N;
    }

    const uint32_t au = as_u[buf];
    const uint32_t bu = bs_u[buf] + b_base_off;
    #pragma unroll
    for (int ksi = 0; ksi < 2; ksi++) {
      uint32_t afr[2][4];
      #pragma unroll
      for (int mi = 0; mi < 2; mi++) {
        uint32_t addr = au + (uint32_t)(a_ln + mi * 16) * 64 +
                        16u * (uint32_t)((2 * ksi + a_hi) ^ a_sw);
        ldsm_x4(afr[mi], addr);
      }
      const uint32_t b_koff = 16u * (uint32_t)((2 * ksi + b_cbit) ^ b_sw);
      #pragma unroll
      for (int nip = 0; nip < 8; nip += 2) {
        uint32_t bq[4];
        ldsm_x4(bq, bu + (uint32_t)(nip * 8 * AK * 4) + b_koff);
        mma_tf32(acc[0][nip],     afr[0], bq[0], bq[1]);
        mma_tf32(acc[0][nip + 1], afr[0], bq[2], bq[3]);
        mma_tf32(acc[1][nip],     afr[1], bq[0], bq[1]);
        mma_tf32(acc[1][nip + 1], afr[1], bq[2], bq[3]);
      }
    }

    if (!last) {
      uint32_t* as = As[buf ^ 1];
      *(uint4*)&as[pd0] = make_uint4(f2tf32(xa0.x), f2tf32(xa0.y), f2tf32(xa0.z), f2tf32(xa0.w));
      *(uint4*)&as[pd1] = make_uint4(f2tf32(xa1.x), f2tf32(xa1.y), f2tf32(xa1.z), f2tf32(xa1.w));
      uint32_t* bs = Bs[buf ^ 1];
      *(uint4*)&bs[bd0] = make_uint4(f2tf32(bw[0]), f2tf32(bw[1]), f2tf32(bw[2]), f2tf32(bw[3]));
      *(uint4*)&bs[bd1] = make_uint4(f2tf32(bw[4]), f2tf32(bw[5]), f2tf32(bw[6]), f2tf32(bw[7]));
      __syncthreads();
      buf ^= 1;
    }
  }

  #pragma unroll
  for (int mi = 0; mi < 2; mi++) {
    #pragma unroll
    for (int ni = 0; ni < 8; ni++) {
      int row = crow + m_base + mi * 16 + g;
      int col = ccol + n_base + ni * 8 + 2 * tc;
      *(float2*)&C[(size_t)row * N + col] =
          make_float2(acc[mi][ni][0], acc[mi][ni][1]);
      *(float2*)&C[(size_t)(row + 8) * N + col] =
          make_float2(acc[mi][ni][2], acc[mi][ni][3]);
    }
  }
}

// ---------------------------------------------------------------------------
// RoPE applied in-place to q and k (first ROT dims of each head)
// ---------------------------------------------------------------------------
__global__ void rope_kernel(float* __restrict__ q, float* __restrict__ k,
                            const float* __restrict__ rot) {
  int idx = blockIdx.x * 256 + threadIdx.x;
  const int total = MROWS * HH * (ROT / 2);
  if (idx >= total) return;
  int i = idx & 15;
  int h = (idx >> 4) & 15;
  int row = idx >> 8;
  int l = row & (LL - 1);

  float f0 = rot[l * ROT + 2 * i];
  float f1 = rot[l * ROT + 2 * i + 1];
  float s0, c0, s1, c1;
  sincosf(f0, &s0, &c0);
  sincosf(f1, &s1, &c1);

  int base = row * DD + h * KK + 2 * i;
  float2 tq = *(float2*)&q[base];
  float2 tk = *(float2*)&k[base];
  float2 oq, ok;
  oq.x = tq.x * c0 - tq.y * s0;
  oq.y = tq.y * c1 + tq.x * s1;
  ok.x = tk.x * c0 - tk.y * s0;
  ok.y = tk.y * c1 + tk.x * s1;
  *(float2*)&q[base] = oq;
  *(float2*)&k[base] = ok;
}

// ---------------------------------------------------------------------------
// Flash attention, TF32 tensor cores + ldmatrix + register-prefetched K/V.
// Per-iteration: STS(prefetched regs) -> bar -> issue LDG for next tile ->
// QK^T + softmax + PV -> bar. Global latency hidden behind compute.
// ---------------------------------------------------------------------------
#define FS 68
#define FA_SMEM_WORDS (128 * FS + 64 * FS + 64 * FS + 128 * FS)
#define FA_SMEM_BYTES (FA_SMEM_WORDS * 4)

__global__ __launch_bounds__(256) void flash_attn_tc(
    const float* __restrict__ gq, const float* __restrict__ gk,
    const float* __restrict__ gv, float* __restrict__ gctx) {
  extern __shared__ uint32_t usm[];
  uint32_t* Qs = usm;               // [128][FS]  Qs[row][d]
  uint32_t* Ks = Qs + 128 * FS;     // [64][FS]   Ks[tok][d]
  uint32_t* Vs = Ks + 64 * FS;      // [64][FS]   Vs[d][tok]
  uint32_t* Ps = Vs + 64 * FS;      // [128][FS]  Ps[row][kv]

  const int tid = threadIdx.x;
  const int warp = tid >> 5, lane = tid & 31;
  const int g = lane >> 2, tc = lane & 3;
  const int qt = blockIdx.x, h = blockIdx.y, b = blockIdx.z;
  const int qrow0 = b * LL + qt * 128;
  const int hoff = h * KK;
  const int wrow = warp * 16;

  // ldmatrix per-lane byte offsets
  const uint32_t a_lnoff = ((wrow + (lane & 15)) * FS + 4 * (lane >> 4)) * 4;
  const uint32_t b_lnoff =
      ((8 * (lane >> 4) + (lane & 7)) * FS + 4 * ((lane >> 3) & 1)) * 4;
  const uint32_t qs_u = s2u(Qs), ks_u = s2u(Ks), vs_u = s2u(Vs), ps_u = s2u(Ps);

  // K/V loader mapping (per thread): token tok, dims [d0, d0+16)
  const int tok = tid >> 2;
  const int d0 = (tid & 3) * 16;
  const float* kv_k = gk + (size_t)(b * LL + tok) * DD + hoff + d0;
  const float* kv_v = gv + (size_t)(b * LL + tok) * DD + hoff + d0;

  // Load Q tile, pre-scaled by 1/sqrt(64)=0.125
  {
    int r = tid >> 1;
    int dq = (tid & 1) * 32;
    const float* src = gq + (size_t)(qrow0 + r) * DD + hoff + dq;
    uint32_t* dst = &Qs[r * FS + dq];
    #pragma unroll
    for (int u = 0; u < 8; u++) {
      float4 x = *(const float4*)(src + 4 * u);
      dst[4 * u + 0] = f2tf32(0.125f * x.x);
      dst[4 * u + 1] = f2tf32(0.125f * x.y);
      dst[4 * u + 2] = f2tf32(0.125f * x.z);
      dst[4 * u + 3] = f2tf32(0.125f * x.w);
    }
  }

  // Prologue: prefetch KV tile 0 into registers
  float4 kr[4], vr[4];
  #pragma unroll
  for (int u = 0; u < 4; u++) {
    kr[u] = *(const float4*)(kv_k + 4 * u);
    vr[u] = *(const float4*)(kv_v + 4 * u);
  }

  float o[8][4];
  #pragma unroll
  for (int ni = 0; ni < 8; ni++)
    #pragma unroll
    for (int r = 0; r < 4; r++) o[ni][r] = 0.0f;
  float mrow0 = -1e30f, mrow1 = -1e30f;
  float lrow0 = 0.0f, lrow1 = 0.0f;

  const int NT = LL / 64;
  for (int t = 0; t < NT; t++) {
    // Store prefetched K [tok][d] and V transposed [d][tok]
    {
      uint32_t* kd = &Ks[tok * FS + d0];
      #pragma unroll
      for (int u = 0; u < 4; u++) {
        kd[4 * u + 0] = f2tf32(kr[u].x);
        kd[4 * u + 1] = f2tf32(kr[u].y);
        kd[4 * u + 2] = f2tf32(kr[u].z);
        kd[4 * u + 3] = f2tf32(kr[u].w);
        Vs[(d0 + 4 * u + 0) * FS + tok] = f2tf32(vr[u].x);
        Vs[(d0 + 4 * u + 1) * FS + tok] = f2tf32(vr[u].y);
        Vs[(d0 + 4 * u + 2) * FS + tok] = f2tf32(vr[u].z);
        Vs[(d0 + 4 * u + 3) * FS + tok] = f2tf32(vr[u].w);
      }
    }
    __syncthreads();   // Ks, Vs (and first-iter Qs) visible

    // Prefetch next KV tile into registers; LDG drains behind the mma work
    if (t + 1 < NT) {
      const float* nk = kv_k + (size_t)(t + 1) * 64 * DD;
      const float* nv = kv_v + (size_t)(t + 1) * 64 * DD;
      #pragma unroll
      for (int u = 0; u < 4; u++) {
        kr[u] = *(const float4*)(nk + 4 * u);
        vr[u] = *(const float4*)(nv + 4 * u);
      }
    }

    // S = Q K^T
    float sacc[8][4];
    #pragma unroll
    for (int ni = 0; ni < 8; ni++)
      #pragma unroll
      for (int r = 0; r < 4; r++) sacc[ni][r] = 0.0f;

    #pragma unroll
    for (int ks = 0; ks < 8; ks++) {
      uint32_t a[4];
      ldsm_x4(a, qs_u + a_lnoff + ks * 32);
      #pragma unroll
      for (int ni = 0; ni < 8; ni += 2) {
        uint32_t bq[4];
        ldsm_x4(bq, ks_u + b_lnoff + (uint32_t)(ni * 8 * FS * 4) + ks * 32);
        mma_tf32(sacc[ni], a, bq[0], bq[1]);
        mma_tf32(sacc[ni + 1], a, bq[2], bq[3]);
      }
    }

    // Warp-local online softmax
    float mx0 = -1e30f, mx1 = -1e30f;
    #pragma unroll
    for (int ni = 0; ni < 8; ni++) {
      mx0 = fmaxf(mx0, fmaxf(sacc[ni][0], sacc[ni][1]));
      mx1 = fmaxf(mx1, fmaxf(sacc[ni][2], sacc[ni][3]));
    }
    mx0 = fmaxf(mx0, __shfl_xor_sync(0xffffffffu, mx0, 1));
    mx0 = fmaxf(mx0, __shfl_xor_sync(0xffffffffu, mx0, 2));
    mx1 = fmaxf(mx1, __shfl_xor_sync(0xffffffffu, mx1, 1));
    mx1 = fmaxf(mx1, __shfl_xor_sync(0xffffffffu, mx1, 2));

    float mn0 = fmaxf(mrow0, mx0);
    float mn1 = fmaxf(mrow1, mx1);
    float corr0 = __expf(mrow0 - mn0);
    float corr1 = __expf(mrow1 - mn1);
    mrow0 = mn0; mrow1 = mn1;

    float ls0 = 0.0f, ls1 = 0.0f;
    #pragma unroll
    for (int ni = 0; ni < 8; ni++) {
      float p00 = __expf(sacc[ni][0] - mn0);
      float p01 = __expf(sacc[ni][1] - mn0);
      float p10 = __expf(sacc[ni][2] - mn1);
      float p11 = __expf(sacc[ni][3] - mn1);
      ls0 += p00 + p01;
      ls1 += p10 + p11;
      int col = ni * 8 + 2 * tc;
      uint32_t* p0 = &Ps[(wrow + g) * FS + col];
      p0[0] = f2tf32(p00); p0[1] = f2tf32(p01);
      uint32_t* p1 = &Ps[(wrow + g + 8) * FS + col];
      p1[0] = f2tf32(p10); p1[1] = f2tf32(p11);
    }
    ls0 += __shfl_xor_sync(0xffffffffu, ls0, 1);
    ls0 += __shfl_xor_sync(0xffffffffu, ls0, 2);
    ls1 += __shfl_xor_sync(0xffffffffu, ls1, 1);
    ls1 += __shfl_xor_sync(0xffffffffu, ls1, 2);
    lrow0 = lrow0 * corr0 + ls0;
    lrow1 = lrow1 * corr1 + ls1;

    #pragma unroll
    for (int ni = 0; ni < 8; ni++) {
      o[ni][0] *= corr0; o[ni][1] *= corr0;
      o[ni][2] *= corr1; o[ni][3] *= corr1;
    }
    __syncwarp();

    // O += P @ V
    #pragma unroll
    for (int ks = 0; ks < 8; ks++) {
      uint32_t a[4];
      ldsm_x4(a, ps_u + a_lnoff + ks * 32);
      #pragma unroll
      for (int ni = 0; ni < 8; ni += 2) {
        uint32_t bv[4];
        ldsm_x4(bv, vs_u + b_lnoff + (uint32_t)(ni * 8 * FS * 4) + ks * 32);
        mma_tf32(o[ni], a, bv[0], bv[1]);
        mma_tf32(o[ni + 1], a, bv[2], bv[3]);
      }
    }
    __syncthreads();   // Ks/Vs reads done before next iter's stores
  }

  // Normalize and store
  float inv0 = 1.0f / lrow0;
  float inv1 = 1.0f / lrow1;
  #pragma unroll
  for (int ni = 0; ni < 8; ni++) {
    int col = hoff + ni * 8 + 2 * tc;
    int row0 = qrow0 + wrow + g;
    *(float2*)&gctx[(size_t)row0 * DD + col] =
        make_float2(o[ni][0] * inv0, o[ni][1] * inv0);
    *(float2*)&gctx[(size_t)(row0 + 8) * DD + col] =
        make_float2(o[ni][2] * inv1, o[ni][3] * inv1);
  }
}

// ---------------------------------------------------------------------------
extern "C" void kernel_launch(void* const* d_in, const int* in_sizes, int n_in,
                              void* d_out, int out_size) {
  const float* query    = (const float*)d_in[0];
  const float* key      = (const float*)d_in[1];
  const float* value    = (const float*)d_in[2];
  const float* rot      = (const float*)d_in[3];
  const float* q_kernel = (const float*)d_in[4];
  const float* k_kernel = (const float*)d_in[5];
  const float* v_kernel = (const float*)d_in[6];
  const float* o_kernel = (const float*)d_in[7];
  float* out = (float*)d_out;

  float *pq, *pk, *pv, *pctx;
  cudaGetSymbolAddress((void**)&pq, g_q);
  cudaGetSymbolAddress((void**)&pk, g_k);
  cudaGetSymbolAddress((void**)&pv, g_v);
  cudaGetSymbolAddress((void**)&pctx, g_ctx);

  // QKV projections fused into one launch (grid.z selects A/B/C)
  sgemm_tf32_db<<<dim3(DD / 128, MROWS / 128, 3), 256>>>(
      query, key, value, q_kernel, k_kernel, v_kernel, pq, pk, pv,
      MROWS, DD, DD);

  // RoPE on q, k
  {
    int total = MROWS * HH * (ROT / 2);
    rope_kernel<<<(total + 255) / 256, 256>>>(pq, pk, rot);
  }

  // Flash attention (tf32 tensor cores + ldmatrix + KV register prefetch)
  cudaFuncSetAttribute(flash_attn_tc, cudaFuncAttributeMaxDynamicSharedMemorySize,
                       FA_SMEM_BYTES);
  flash_attn_tc<<<dim3(LL / 128, HH, BB), 256, FA_SMEM_BYTES>>>(pq, pk, pv, pctx);

  // Output projection
  sgemm_tf32_db<<<dim3(DD / 128, MROWS / 128, 1), 256>>>(
      pctx, pctx, pctx, o_kernel, o_kernel, o_kernel, out, out, out,
      MROWS, DD, DD);
}

// round 13
// speedup vs baseline: 3.0787x; 1.0169x over previous
#include <cuda_runtime.h>
#include <cuda_fp16.h>
#include <math.h>
#include <stdint.h>

// Problem constants
#define BB 2
#define LL 2048
#define DD 1024
#define HH 16
#define KK 64
#define ROT 32
#define MROWS (BB * LL)   // 4096

// Scratch (static device arrays: allocation-free)
__device__ float g_q[MROWS * DD];
__device__ float g_k[MROWS * DD];
__device__ float g_v[MROWS * DD];
__device__ float g_ctx[MROWS * DD];

__device__ __forceinline__ uint32_t f2tf32(float f) {
  uint32_t u;
  asm("cvt.rna.tf32.f32 %0, %1;" : "=r"(u) : "f"(f));
  return u;
}

__device__ __forceinline__ uint32_t f2h2(float lo, float hi) {
  __half2 h = __floats2half2_rn(lo, hi);
  return *reinterpret_cast<uint32_t*>(&h);
}

__device__ __forceinline__ void mma_tf32(float c[4], const uint32_t a[4],
                                         uint32_t b0, uint32_t b1) {
  asm("mma.sync.aligned.m16n8k8.row.col.f32.tf32.tf32.f32 "
      "{%0,%1,%2,%3},{%4,%5,%6,%7},{%8,%9},{%0,%1,%2,%3};"
      : "+f"(c[0]), "+f"(c[1]), "+f"(c[2]), "+f"(c[3])
      : "r"(a[0]), "r"(a[1]), "r"(a[2]), "r"(a[3]), "r"(b0), "r"(b1));
}

__device__ __forceinline__ void mma_f16(float c[4], const uint32_t a[4],
                                        uint32_t b0, uint32_t b1) {
  asm("mma.sync.aligned.m16n8k16.row.col.f32.f16.f16.f32 "
      "{%0,%1,%2,%3},{%4,%5,%6,%7},{%8,%9},{%0,%1,%2,%3};"
      : "+f"(c[0]), "+f"(c[1]), "+f"(c[2]), "+f"(c[3])
      : "r"(a[0]), "r"(a[1]), "r"(a[2]), "r"(a[3]), "r"(b0), "r"(b1));
}

__device__ __forceinline__ void ldsm_x4(uint32_t* r, uint32_t addr) {
  asm volatile("ldmatrix.sync.aligned.m8n8.x4.shared.b16 {%0,%1,%2,%3}, [%4];"
               : "=r"(r[0]), "=r"(r[1]), "=r"(r[2]), "=r"(r[3]) : "r"(addr));
}

__device__ __forceinline__ uint32_t s2u(const void* p) {
  return (uint32_t)__cvta_generic_to_shared(p);
}

// ---------------------------------------------------------------------------
// FP16 tensor-core GEMM, double-buffered, ldmatrix both operands.
// C[M,N] = A[M,Kd]*B[Kd,N] (fp32 in/out, fp16 mma with fp32 accumulate).
// Block 128x128, BK=32, 256 threads, 8 warps (4m x 2n), warp tile 32x64,
// m16n8k16 fragments.
// smem: A[m][32 kh], B[n][32 kh]; row stride 24 words (96B = 64B data+32B pad)
// with chunk swizzle c ^ ((row>>2)&3) -> conflict-free STS.128 + ldmatrix.
// grid.z selects (A,B,C).
// ---------------------------------------------------------------------------
#define GSTR 24   // words per smem row (96 bytes)

__global__ __launch_bounds__(256, 2) void gemm_f16_db(
    const float* __restrict__ A0, const float* __restrict__ A1,
    const float* __restrict__ A2, const float* __restrict__ B0,
    const float* __restrict__ B1, const float* __restrict__ B2,
    float* __restrict__ C0, float* __restrict__ C1, float* __restrict__ C2,
    int M, int N, int Kd) {
  __shared__ uint32_t As[2][128 * GSTR];
  __shared__ uint32_t Bs[2][128 * GSTR];

  const int z = blockIdx.z;
  const float* A = (z == 0) ? A0 : (z == 1) ? A1 : A2;
  const float* B = (z == 0) ? B0 : (z == 1) ? B1 : B2;
  float* C = (z == 0) ? C0 : (z == 1) ? C1 : C2;

  const int tid = threadIdx.x;
  const int warp = tid >> 5, lane = tid & 31;
  const int g = lane >> 2, tc = lane & 3;
  const int wm = warp & 3, wn = warp >> 2;
  const int m_base = wm * 32;
  const int n_base = wn * 64;
  const int crow = blockIdx.y * 128;
  const int ccol = blockIdx.x * 128;

  // Producer: thread -> row pr (0..127), k-half pkh (k 16*pkh..16*pkh+15)
  const int pr = tid & 127;
  const int pkh = tid >> 7;
  const int psw = (pr >> 2) & 3;
  const uint32_t pw0 = pr * GSTR + 4 * ((2 * pkh) ^ psw);
  const uint32_t pw1 = pr * GSTR + 4 * ((2 * pkh + 1) ^ psw);
  const float* ApG = A + (size_t)(crow + pr) * Kd + 16 * pkh;
  const float* BpG = B + (size_t)(16 * pkh) * N + ccol + pr;

  // A consumer (ldmatrix x4): lanes0-7 rows0-7 klo, 8-15 rows8-15 klo,
  // 16-23 rows0-7 khi, 24-31 rows8-15 khi.
  const uint32_t a_row_b = (uint32_t)(m_base + (lane & 15)) * 96;
  const int a_sw = ((lane & 15) >> 2) & 3;
  const int a_kb = lane >> 4;
  // B consumer: lanes0-7 n0-7 klo, 8-15 n0-7 khi, 16-23 n8-15 klo, 24-31 khi.
  const uint32_t b_row_b =
      (uint32_t)(n_base + 8 * (lane >> 4) + (lane & 7)) * 96;
  const int b_kb = (lane >> 3) & 1;
  const int b_sw = (2 * (lane >> 4) + ((lane & 7) >> 2)) & 3;

  float acc[2][8][4];
  #pragma unroll
  for (int mi = 0; mi < 2; mi++)
    #pragma unroll
    for (int ni = 0; ni < 8; ni++)
      #pragma unroll
      for (int r = 0; r < 4; r++) acc[mi][ni][r] = 0.0f;

  // Prologue: tile 0 -> buffer 0
  float4 af[4];
  float bf[16];
  #pragma unroll
  for (int j = 0; j < 4; j++) af[j] = *(const float4*)(ApG + 4 * j);
  #pragma unroll
  for (int j = 0; j < 16; j++) bf[j] = BpG[(size_t)j * N];
  ApG += 32;
  BpG += (size_t)32 * N;
  {
    uint32_t* as = As[0];
    *(uint4*)&as[pw0] = make_uint4(f2h2(af[0].x, af[0].y), f2h2(af[0].z, af[0].w),
                                   f2h2(af[1].x, af[1].y), f2h2(af[1].z, af[1].w));
    *(uint4*)&as[pw1] = make_uint4(f2h2(af[2].x, af[2].y), f2h2(af[2].z, af[2].w),
                                   f2h2(af[3].x, af[3].y), f2h2(af[3].z, af[3].w));
    uint32_t* bs = Bs[0];
    *(uint4*)&bs[pw0] = make_uint4(f2h2(bf[0], bf[1]), f2h2(bf[2], bf[3]),
                                   f2h2(bf[4], bf[5]), f2h2(bf[6], bf[7]));
    *(uint4*)&bs[pw1] = make_uint4(f2h2(bf[8], bf[9]), f2h2(bf[10], bf[11]),
                                   f2h2(bf[12], bf[13]), f2h2(bf[14], bf[15]));
  }
  __syncthreads();

  const uint32_t as_u[2] = {s2u(As[0]), s2u(As[1])};
  const uint32_t bs_u[2] = {s2u(Bs[0]), s2u(Bs[1])};

  int buf = 0;
  const int iters = Kd / 32;
  for (int it = 0; it < iters; it++) {
    const bool last = (it == iters - 1);
    if (!last) {
      #pragma unroll
      for (int j = 0; j < 4; j++) af[j] = *(const float4*)(ApG + 4 * j);
      #pragma unroll
      for (int j = 0; j < 16; j++) bf[j] = BpG[(size_t)j * N];
      ApG += 32;
      BpG += (size_t)32 * N;
    }

    const uint32_t au = as_u[buf];
    const uint32_t bu = bs_u[buf];
    #pragma unroll
    for (int s = 0; s < 2; s++) {
      uint32_t afr[2][4];
      const uint32_t a_k = 16u * (uint32_t)((2 * s + a_kb) ^ a_sw);
      ldsm_x4(afr[0], au + a_row_b + a_k);
      ldsm_x4(afr[1], au + a_row_b + 1536 + a_k);
      const uint32_t b_k = 16u * (uint32_t)((2 * s + b_kb) ^ b_sw);
      #pragma unroll
      for (int p = 0; p < 4; p++) {
        uint32_t bq[4];
        ldsm_x4(bq, bu + b_row_b + (uint32_t)(p * 1536) + b_k);
        mma_f16(acc[0][2 * p],     afr[0], bq[0], bq[1]);
        mma_f16(acc[0][2 * p + 1], afr[0], bq[2], bq[3]);
        mma_f16(acc[1][2 * p],     afr[1], bq[0], bq[1]);
        mma_f16(acc[1][2 * p + 1], afr[1], bq[2], bq[3]);
      }
    }

    if (!last) {
      uint32_t* as = As[buf ^ 1];
      *(uint4*)&as[pw0] = make_uint4(f2h2(af[0].x, af[0].y), f2h2(af[0].z, af[0].w),
                                     f2h2(af[1].x, af[1].y), f2h2(af[1].z, af[1].w));
      *(uint4*)&as[pw1] = make_uint4(f2h2(af[2].x, af[2].y), f2h2(af[2].z, af[2].w),
                                     f2h2(af[3].x, af[3].y), f2h2(af[3].z, af[3].w));
      uint32_t* bs = Bs[buf ^ 1];
      *(uint4*)&bs[pw0] = make_uint4(f2h2(bf[0], bf[1]), f2h2(bf[2], bf[3]),
                                     f2h2(bf[4], bf[5]), f2h2(bf[6], bf[7]));
      *(uint4*)&bs[pw1] = make_uint4(f2h2(bf[8], bf[9]), f2h2(bf[10], bf[11]),
                                     f2h2(bf[12], bf[13]), f2h2(bf[14], bf[15]));
      __syncthreads();
      buf ^= 1;
    }
  }

  #pragma unroll
  for (int mi = 0; mi < 2; mi++) {
    #pragma unroll
    for (int ni = 0; ni < 8; ni++) {
      int row = crow + m_base + mi * 16 + g;
      int col = ccol + n_base + ni * 8 + 2 * tc;
      *(float2*)&C[(size_t)row * N + col] =
          make_float2(acc[mi][ni][0], acc[mi][ni][1]);
      *(float2*)&C[(size_t)(row + 8) * N + col] =
          make_float2(acc[mi][ni][2], acc[mi][ni][3]);
    }
  }
}

// ---------------------------------------------------------------------------
// RoPE applied in-place to q and k (first ROT dims of each head)
// ---------------------------------------------------------------------------
__global__ void rope_kernel(float* __restrict__ q, float* __restrict__ k,
                            const float* __restrict__ rot) {
  int idx = blockIdx.x * 256 + threadIdx.x;
  const int total = MROWS * HH * (ROT / 2);
  if (idx >= total) return;
  int i = idx & 15;
  int h = (idx >> 4) & 15;
  int row = idx >> 8;
  int l = row & (LL - 1);

  float f0 = rot[l * ROT + 2 * i];
  float f1 = rot[l * ROT + 2 * i + 1];
  float s0, c0, s1, c1;
  sincosf(f0, &s0, &c0);
  sincosf(f1, &s1, &c1);

  int base = row * DD + h * KK + 2 * i;
  float2 tq = *(float2*)&q[base];
  float2 tk = *(float2*)&k[base];
  float2 oq, ok;
  oq.x = tq.x * c0 - tq.y * s0;
  oq.y = tq.y * c1 + tq.x * s1;
  ok.x = tk.x * c0 - tk.y * s0;
  ok.y = tk.y * c1 + tk.x * s1;
  *(float2*)&q[base] = oq;
  *(float2*)&k[base] = ok;
}

// ---------------------------------------------------------------------------
// Flash attention, TF32 tensor cores + ldmatrix + register-prefetched K/V.
// (Unchanged from R11 passing version, 662us.)
// ---------------------------------------------------------------------------
#define FS 68
#define FA_SMEM_WORDS (128 * FS + 64 * FS + 64 * FS + 128 * FS)
#define FA_SMEM_BYTES (FA_SMEM_WORDS * 4)

__global__ __launch_bounds__(256) void flash_attn_tc(
    const float* __restrict__ gq, const float* __restrict__ gk,
    const float* __restrict__ gv, float* __restrict__ gctx) {
  extern __shared__ uint32_t usm[];
  uint32_t* Qs = usm;               // [128][FS]  Qs[row][d]
  uint32_t* Ks = Qs + 128 * FS;     // [64][FS]   Ks[tok][d]
  uint32_t* Vs = Ks + 64 * FS;      // [64][FS]   Vs[d][tok]
  uint32_t* Ps = Vs + 64 * FS;      // [128][FS]  Ps[row][kv]

  const int tid = threadIdx.x;
  const int warp = tid >> 5, lane = tid & 31;
  const int g = lane >> 2, tc = lane & 3;
  const int qt = blockIdx.x, h = blockIdx.y, b = blockIdx.z;
  const int qrow0 = b * LL + qt * 128;
  const int hoff = h * KK;
  const int wrow = warp * 16;

  const uint32_t a_lnoff = ((wrow + (lane & 15)) * FS + 4 * (lane >> 4)) * 4;
  const uint32_t b_lnoff =
      ((8 * (lane >> 4) + (lane & 7)) * FS + 4 * ((lane >> 3) & 1)) * 4;
  const uint32_t qs_u = s2u(Qs), ks_u = s2u(Ks), vs_u = s2u(Vs), ps_u = s2u(Ps);

  const int tok = tid >> 2;
  const int d0 = (tid & 3) * 16;
  const float* kv_k = gk + (size_t)(b * LL + tok) * DD + hoff + d0;
  const float* kv_v = gv + (size_t)(b * LL + tok) * DD + hoff + d0;

  {
    int r = tid >> 1;
    int dq = (tid & 1) * 32;
    const float* src = gq + (size_t)(qrow0 + r) * DD + hoff + dq;
    uint32_t* dst = &Qs[r * FS + dq];
    #pragma unroll
    for (int u = 0; u < 8; u++) {
      float4 x = *(const float4*)(src + 4 * u);
      dst[4 * u + 0] = f2tf32(0.125f * x.x);
      dst[4 * u + 1] = f2tf32(0.125f * x.y);
      dst[4 * u + 2] = f2tf32(0.125f * x.z);
      dst[4 * u + 3] = f2tf32(0.125f * x.w);
    }
  }

  float4 kr[4], vr[4];
  #pragma unroll
  for (int u = 0; u < 4; u++) {
    kr[u] = *(const float4*)(kv_k + 4 * u);
    vr[u] = *(const float4*)(kv_v + 4 * u);
  }

  float o[8][4];
  #pragma unroll
  for (int ni = 0; ni < 8; ni++)
    #pragma unroll
    for (int r = 0; r < 4; r++) o[ni][r] = 0.0f;
  float mrow0 = -1e30f, mrow1 = -1e30f;
  float lrow0 = 0.0f, lrow1 = 0.0f;

  const int NT = LL / 64;
  for (int t = 0; t < NT; t++) {
    {
      uint32_t* kd = &Ks[tok * FS + d0];
      #pragma unroll
      for (int u = 0; u < 4; u++) {
        kd[4 * u + 0] = f2tf32(kr[u].x);
        kd[4 * u + 1] = f2tf32(kr[u].y);
        kd[4 * u + 2] = f2tf32(kr[u].z);
        kd[4 * u + 3] = f2tf32(kr[u].w);
        Vs[(d0 + 4 * u + 0) * FS + tok] = f2tf32(vr[u].x);
        Vs[(d0 + 4 * u + 1) * FS + tok] = f2tf32(vr[u].y);
        Vs[(d0 + 4 * u + 2) * FS + tok] = f2tf32(vr[u].z);
        Vs[(d0 + 4 * u + 3) * FS + tok] = f2tf32(vr[u].w);
      }
    }
    __syncthreads();

    if (t + 1 < NT) {
      const float* nk = kv_k + (size_t)(t + 1) * 64 * DD;
      const float* nv = kv_v + (size_t)(t + 1) * 64 * DD;
      #pragma unroll
      for (int u = 0; u < 4; u++) {
        kr[u] = *(const float4*)(nk + 4 * u);
        vr[u] = *(const float4*)(nv + 4 * u);
      }
    }

    float sacc[8][4];
    #pragma unroll
    for (int ni = 0; ni < 8; ni++)
      #pragma unroll
      for (int r = 0; r < 4; r++) sacc[ni][r] = 0.0f;

    #pragma unroll
    for (int ks = 0; ks < 8; ks++) {
      uint32_t a[4];
      ldsm_x4(a, qs_u + a_lnoff + ks * 32);
      #pragma unroll
      for (int ni = 0; ni < 8; ni += 2) {
        uint32_t bq[4];
        ldsm_x4(bq, ks_u + b_lnoff + (uint32_t)(ni * 8 * FS * 4) + ks * 32);
        mma_tf32(sacc[ni], a, bq[0], bq[1]);
        mma_tf32(sacc[ni + 1], a, bq[2], bq[3]);
      }
    }

    float mx0 = -1e30f, mx1 = -1e30f;
    #pragma unroll
    for (int ni = 0; ni < 8; ni++) {
      mx0 = fmaxf(mx0, fmaxf(sacc[ni][0], sacc[ni][1]));
      mx1 = fmaxf(mx1, fmaxf(sacc[ni][2], sacc[ni][3]));
    }
    mx0 = fmaxf(mx0, __shfl_xor_sync(0xffffffffu, mx0, 1));
    mx0 = fmaxf(mx0, __shfl_xor_sync(0xffffffffu, mx0, 2));
    mx1 = fmaxf(mx1, __shfl_xor_sync(0xffffffffu, mx1, 1));
    mx1 = fmaxf(mx1, __shfl_xor_sync(0xffffffffu, mx1, 2));

    float mn0 = fmaxf(mrow0, mx0);
    float mn1 = fmaxf(mrow1, mx1);
    float corr0 = __expf(mrow0 - mn0);
    float corr1 = __expf(mrow1 - mn1);
    mrow0 = mn0; mrow1 = mn1;

    float ls0 = 0.0f, ls1 = 0.0f;
    #pragma unroll
    for (int ni = 0; ni < 8; ni++) {
      float p00 = __expf(sacc[ni][0] - mn0);
      float p01 = __expf(sacc[ni][1] - mn0);
      float p10 = __expf(sacc[ni][2] - mn1);
      float p11 = __expf(sacc[ni][3] - mn1);
      ls0 += p00 + p01;
      ls1 += p10 + p11;
      int col = ni * 8 + 2 * tc;
      uint32_t* p0 = &Ps[(wrow + g) * FS + col];
      p0[0] = f2tf32(p00); p0[1] = f2tf32(p01);
      uint32_t* p1 = &Ps[(wrow + g + 8) * FS + col];
      p1[0] = f2tf32(p10); p1[1] = f2tf32(p11);
    }
    ls0 += __shfl_xor_sync(0xffffffffu, ls0, 1);
    ls0 += __shfl_xor_sync(0xffffffffu, ls0, 2);
    ls1 += __shfl_xor_sync(0xffffffffu, ls1, 1);
    ls1 += __shfl_xor_sync(0xffffffffu, ls1, 2);
    lrow0 = lrow0 * corr0 + ls0;
    lrow1 = lrow1 * corr1 + ls1;

    #pragma unroll
    for (int ni = 0; ni < 8; ni++) {
      o[ni][0] *= corr0; o[ni][1] *= corr0;
      o[ni][2] *= corr1; o[ni][3] *= corr1;
    }
    __syncwarp();

    #pragma unroll
    for (int ks = 0; ks < 8; ks++) {
      uint32_t a[4];
      ldsm_x4(a, ps_u + a_lnoff + ks * 32);
      #pragma unroll
      for (int ni = 0; ni < 8; ni += 2) {
        uint32_t bv[4];
        ldsm_x4(bv, vs_u + b_lnoff + (uint32_t)(ni * 8 * FS * 4) + ks * 32);
        mma_tf32(o[ni], a, bv[0], bv[1]);
        mma_tf32(o[ni + 1], a, bv[2], bv[3]);
      }
    }
    __syncthreads();
  }

  float inv0 = 1.0f / lrow0;
  float inv1 = 1.0f / lrow1;
  #pragma unroll
  for (int ni = 0; ni < 8; ni++) {
    int col = hoff + ni * 8 + 2 * tc;
    int row0 = qrow0 + wrow + g;
    *(float2*)&gctx[(size_t)row0 * DD + col] =
        make_float2(o[ni][0] * inv0, o[ni][1] * inv0);
    *(float2*)&gctx[(size_t)(row0 + 8) * DD + col] =
        make_float2(o[ni][2] * inv1, o[ni][3] * inv1);
  }
}

// ---------------------------------------------------------------------------
extern "C" void kernel_launch(void* const* d_in, const int* in_sizes, int n_in,
                              void* d_out, int out_size) {
  const float* query    = (const float*)d_in[0];
  const float* key      = (const float*)d_in[1];
  const float* value    = (const float*)d_in[2];
  const float* rot      = (const float*)d_in[3];
  const float* q_kernel = (const float*)d_in[4];
  const float* k_kernel = (const float*)d_in[5];
  const float* v_kernel = (const float*)d_in[6];
  const float* o_kernel = (const float*)d_in[7];
  float* out = (float*)d_out;

  float *pq, *pk, *pv, *pctx;
  cudaGetSymbolAddress((void**)&pq, g_q);
  cudaGetSymbolAddress((void**)&pk, g_k);
  cudaGetSymbolAddress((void**)&pv, g_v);
  cudaGetSymbolAddress((void**)&pctx, g_ctx);

  // QKV projections fused into one launch (grid.z selects A/B/C), fp16 mma
  gemm_f16_db<<<dim3(DD / 128, MROWS / 128, 3), 256>>>(
      query, key, value, q_kernel, k_kernel, v_kernel, pq, pk, pv,
      MROWS, DD, DD);

  // RoPE on q, k
  {
    int total = MROWS * HH * (ROT / 2);
    rope_kernel<<<(total + 255) / 256, 256>>>(pq, pk, rot);
  }

  // Flash attention (tf32 tensor cores + ldmatrix + KV register prefetch)
  cudaFuncSetAttribute(flash_attn_tc, cudaFuncAttributeMaxDynamicSharedMemorySize,
                       FA_SMEM_BYTES);
  flash_attn_tc<<<dim3(LL / 128, HH, BB), 256, FA_SMEM_BYTES>>>(pq, pk, pv, pctx);

  // Output projection (fp16 mma)
  gemm_f16_db<<<dim3(DD / 128, MROWS / 128, 1), 256>>>(
      pctx, pctx, pctx, o_kernel, o_kernel, o_kernel, out, out, out,
      MROWS, DD, DD);
}

// round 14
// speedup vs baseline: 3.5472x; 1.1522x over previous
#include <cuda_runtime.h>
#include <cuda_fp16.h>
#include <math.h>
#include <stdint.h>

// Problem constants
#define BB 2
#define LL 2048
#define DD 1024
#define HH 16
#define KK 64
#define ROT 32
#define MROWS (BB * LL)   // 4096

// Scratch (static device arrays: allocation-free)
__device__ float g_q[MROWS * DD];
__device__ float g_k[MROWS * DD];
__device__ float g_v[MROWS * DD];
__device__ float g_ctx[MROWS * DD];

__device__ __forceinline__ uint32_t f2h2(float lo, float hi) {
  __half2 h = __floats2half2_rn(lo, hi);
  return *reinterpret_cast<uint32_t*>(&h);
}

__device__ __forceinline__ void mma_f16(float c[4], const uint32_t a[4],
                                        uint32_t b0, uint32_t b1) {
  asm("mma.sync.aligned.m16n8k16.row.col.f32.f16.f16.f32 "
      "{%0,%1,%2,%3},{%4,%5,%6,%7},{%8,%9},{%0,%1,%2,%3};"
      : "+f"(c[0]), "+f"(c[1]), "+f"(c[2]), "+f"(c[3])
      : "r"(a[0]), "r"(a[1]), "r"(a[2]), "r"(a[3]), "r"(b0), "r"(b1));
}

__device__ __forceinline__ void ldsm_x4(uint32_t* r, uint32_t addr) {
  asm volatile("ldmatrix.sync.aligned.m8n8.x4.shared.b16 {%0,%1,%2,%3}, [%4];"
               : "=r"(r[0]), "=r"(r[1]), "=r"(r[2]), "=r"(r[3]) : "r"(addr));
}

__device__ __forceinline__ uint32_t s2u(const void* p) {
  return (uint32_t)__cvta_generic_to_shared(p);
}

// ---------------------------------------------------------------------------
// FP16 tensor-core GEMM, double-buffered, ldmatrix both operands.
// (Unchanged from R13 passing version.)
// ---------------------------------------------------------------------------
#define GSTR 24   // words per smem row (96 bytes)

__global__ __launch_bounds__(256, 2) void gemm_f16_db(
    const float* __restrict__ A0, const float* __restrict__ A1,
    const float* __restrict__ A2, const float* __restrict__ B0,
    const float* __restrict__ B1, const float* __restrict__ B2,
    float* __restrict__ C0, float* __restrict__ C1, float* __restrict__ C2,
    int M, int N, int Kd) {
  __shared__ uint32_t As[2][128 * GSTR];
  __shared__ uint32_t Bs[2][128 * GSTR];

  const int z = blockIdx.z;
  const float* A = (z == 0) ? A0 : (z == 1) ? A1 : A2;
  const float* B = (z == 0) ? B0 : (z == 1) ? B1 : B2;
  float* C = (z == 0) ? C0 : (z == 1) ? C1 : C2;

  const int tid = threadIdx.x;
  const int warp = tid >> 5, lane = tid & 31;
  const int g = lane >> 2, tc = lane & 3;
  const int wm = warp & 3, wn = warp >> 2;
  const int m_base = wm * 32;
  const int n_base = wn * 64;
  const int crow = blockIdx.y * 128;
  const int ccol = blockIdx.x * 128;

  const int pr = tid & 127;
  const int pkh = tid >> 7;
  const int psw = (pr >> 2) & 3;
  const uint32_t pw0 = pr * GSTR + 4 * ((2 * pkh) ^ psw);
  const uint32_t pw1 = pr * GSTR + 4 * ((2 * pkh + 1) ^ psw);
  const float* ApG = A + (size_t)(crow + pr) * Kd + 16 * pkh;
  const float* BpG = B + (size_t)(16 * pkh) * N + ccol + pr;

  const uint32_t a_row_b = (uint32_t)(m_base + (lane & 15)) * 96;
  const int a_sw = ((lane & 15) >> 2) & 3;
  const int a_kb = lane >> 4;
  const uint32_t b_row_b =
      (uint32_t)(n_base + 8 * (lane >> 4) + (lane & 7)) * 96;
  const int b_kb = (lane >> 3) & 1;
  const int b_sw = (2 * (lane >> 4) + ((lane & 7) >> 2)) & 3;

  float acc[2][8][4];
  #pragma unroll
  for (int mi = 0; mi < 2; mi++)
    #pragma unroll
    for (int ni = 0; ni < 8; ni++)
      #pragma unroll
      for (int r = 0; r < 4; r++) acc[mi][ni][r] = 0.0f;

  float4 af[4];
  float bf[16];
  #pragma unroll
  for (int j = 0; j < 4; j++) af[j] = *(const float4*)(ApG + 4 * j);
  #pragma unroll
  for (int j = 0; j < 16; j++) bf[j] = BpG[(size_t)j * N];
  ApG += 32;
  BpG += (size_t)32 * N;
  {
    uint32_t* as = As[0];
    *(uint4*)&as[pw0] = make_uint4(f2h2(af[0].x, af[0].y), f2h2(af[0].z, af[0].w),
                                   f2h2(af[1].x, af[1].y), f2h2(af[1].z, af[1].w));
    *(uint4*)&as[pw1] = make_uint4(f2h2(af[2].x, af[2].y), f2h2(af[2].z, af[2].w),
                                   f2h2(af[3].x, af[3].y), f2h2(af[3].z, af[3].w));
    uint32_t* bs = Bs[0];
    *(uint4*)&bs[pw0] = make_uint4(f2h2(bf[0], bf[1]), f2h2(bf[2], bf[3]),
                                   f2h2(bf[4], bf[5]), f2h2(bf[6], bf[7]));
    *(uint4*)&bs[pw1] = make_uint4(f2h2(bf[8], bf[9]), f2h2(bf[10], bf[11]),
                                   f2h2(bf[12], bf[13]), f2h2(bf[14], bf[15]));
  }
  __syncthreads();

  const uint32_t as_u[2] = {s2u(As[0]), s2u(As[1])};
  const uint32_t bs_u[2] = {s2u(Bs[0]), s2u(Bs[1])};

  int buf = 0;
  const int iters = Kd / 32;
  for (int it = 0; it < iters; it++) {
    const bool last = (it == iters - 1);
    if (!last) {
      #pragma unroll
      for (int j = 0; j < 4; j++) af[j] = *(const float4*)(ApG + 4 * j);
      #pragma unroll
      for (int j = 0; j < 16; j++) bf[j] = BpG[(size_t)j * N];
      ApG += 32;
      BpG += (size_t)32 * N;
    }

    const uint32_t au = as_u[buf];
    const uint32_t bu = bs_u[buf];
    #pragma unroll
    for (int s = 0; s < 2; s++) {
      uint32_t afr[2][4];
      const uint32_t a_k = 16u * (uint32_t)((2 * s + a_kb) ^ a_sw);
      ldsm_x4(afr[0], au + a_row_b + a_k);
      ldsm_x4(afr[1], au + a_row_b + 1536 + a_k);
      const uint32_t b_k = 16u * (uint32_t)((2 * s + b_kb) ^ b_sw);
      #pragma unroll
      for (int p = 0; p < 4; p++) {
        uint32_t bq[4];
        ldsm_x4(bq, bu + b_row_b + (uint32_t)(p * 1536) + b_k);
        mma_f16(acc[0][2 * p],     afr[0], bq[0], bq[1]);
        mma_f16(acc[0][2 * p + 1], afr[0], bq[2], bq[3]);
        mma_f16(acc[1][2 * p],     afr[1], bq[0], bq[1]);
        mma_f16(acc[1][2 * p + 1], afr[1], bq[2], bq[3]);
      }
    }

    if (!last) {
      uint32_t* as = As[buf ^ 1];
      *(uint4*)&as[pw0] = make_uint4(f2h2(af[0].x, af[0].y), f2h2(af[0].z, af[0].w),
                                     f2h2(af[1].x, af[1].y), f2h2(af[1].z, af[1].w));
      *(uint4*)&as[pw1] = make_uint4(f2h2(af[2].x, af[2].y), f2h2(af[2].z, af[2].w),
                                     f2h2(af[3].x, af[3].y), f2h2(af[3].z, af[3].w));
      uint32_t* bs = Bs[buf ^ 1];
      *(uint4*)&bs[pw0] = make_uint4(f2h2(bf[0], bf[1]), f2h2(bf[2], bf[3]),
                                     f2h2(bf[4], bf[5]), f2h2(bf[6], bf[7]));
      *(uint4*)&bs[pw1] = make_uint4(f2h2(bf[8], bf[9]), f2h2(bf[10], bf[11]),
                                     f2h2(bf[12], bf[13]), f2h2(bf[14], bf[15]));
      __syncthreads();
      buf ^= 1;
    }
  }

  #pragma unroll
  for (int mi = 0; mi < 2; mi++) {
    #pragma unroll
    for (int ni = 0; ni < 8; ni++) {
      int row = crow + m_base + mi * 16 + g;
      int col = ccol + n_base + ni * 8 + 2 * tc;
      *(float2*)&C[(size_t)row * N + col] =
          make_float2(acc[mi][ni][0], acc[mi][ni][1]);
      *(float2*)&C[(size_t)(row + 8) * N + col] =
          make_float2(acc[mi][ni][2], acc[mi][ni][3]);
    }
  }
}

// ---------------------------------------------------------------------------
// RoPE applied in-place to q and k (first ROT dims of each head)
// ---------------------------------------------------------------------------
__global__ void rope_kernel(float* __restrict__ q, float* __restrict__ k,
                            const float* __restrict__ rot) {
  int idx = blockIdx.x * 256 + threadIdx.x;
  const int total = MROWS * HH * (ROT / 2);
  if (idx >= total) return;
  int i = idx & 15;
  int h = (idx >> 4) & 15;
  int row = idx >> 8;
  int l = row & (LL - 1);

  float f0 = rot[l * ROT + 2 * i];
  float f1 = rot[l * ROT + 2 * i + 1];
  float s0, c0, s1, c1;
  sincosf(f0, &s0, &c0);
  sincosf(f1, &s1, &c1);

  int base = row * DD + h * KK + 2 * i;
  float2 tq = *(float2*)&q[base];
  float2 tk = *(float2*)&k[base];
  float2 oq, ok;
  oq.x = tq.x * c0 - tq.y * s0;
  oq.y = tq.y * c1 + tq.x * s1;
  ok.x = tk.x * c0 - tk.y * s0;
  ok.y = tk.y * c1 + tk.x * s1;
  *(float2*)&q[base] = oq;
  *(float2*)&k[base] = ok;
}

// ---------------------------------------------------------------------------
// Flash attention, FP16 tensor cores (m16n8k16) + ldmatrix + reg-prefetch KV.
// All tiles half-packed, row stride 36 words (144B; 36 mod 32 = 4 ->
// conflict-free ldmatrix phases, no swizzle).
//   Qs[128 rows][32w]  (d halves, pre-scaled 1/8)
//   Ks[64 tok][32w]    (d halves)
//   Vs[64 d][32w]      (tok halves; V transposed, written via 16-bit stores)
//   Ps[128 rows][32w]  (kv halves, written as half2 words)
// ---------------------------------------------------------------------------
#define HS 36
#define FA_SMEM_WORDS ((128 + 64 + 64 + 128) * HS)
#define FA_SMEM_BYTES (FA_SMEM_WORDS * 4)

__global__ __launch_bounds__(256) void flash_attn_tc(
    const float* __restrict__ gq, const float* __restrict__ gk,
    const float* __restrict__ gv, float* __restrict__ gctx) {
  extern __shared__ uint32_t usm[];
  uint32_t* Qs = usm;               // [128][HS]
  uint32_t* Ks = Qs + 128 * HS;     // [64][HS]
  uint32_t* Vs = Ks + 64 * HS;      // [64][HS]
  uint32_t* Ps = Vs + 64 * HS;      // [128][HS]
  __half* Vs_h = reinterpret_cast<__half*>(Vs);

  const int tid = threadIdx.x;
  const int warp = tid >> 5, lane = tid & 31;
  const int g = lane >> 2, tc = lane & 3;
  const int qt = blockIdx.x, h = blockIdx.y, b = blockIdx.z;
  const int qrow0 = b * LL + qt * 128;
  const int hoff = h * KK;
  const int wrow = warp * 16;

  // ldmatrix byte offsets (A: rows of Q/P; B: rows of K/V)
  const uint32_t a_lnoff = ((wrow + (lane & 15)) * HS + 4 * (lane >> 4)) * 4;
  const uint32_t b_lnoff =
      ((8 * (lane >> 4) + (lane & 7)) * HS + 4 * ((lane >> 3) & 1)) * 4;
  const uint32_t qs_u = s2u(Qs), ks_u = s2u(Ks), vs_u = s2u(Vs), ps_u = s2u(Ps);

  // K/V loader: thread -> token tok, dims [d0, d0+16)
  const int tok = tid >> 2;
  const int d0 = (tid & 3) * 16;
  const float* kv_k = gk + (size_t)(b * LL + tok) * DD + hoff + d0;
  const float* kv_v = gv + (size_t)(b * LL + tok) * DD + hoff + d0;

  // Load Q tile (half-packed, pre-scaled by 0.125)
  {
    int r = tid >> 1;
    int dq = (tid & 1) * 32;
    const float* src = gq + (size_t)(qrow0 + r) * DD + hoff + dq;
    uint32_t* dst = &Qs[r * HS + (dq >> 1)];
    #pragma unroll
    for (int u = 0; u < 8; u++) {
      float4 x = *(const float4*)(src + 4 * u);
      dst[2 * u + 0] = f2h2(0.125f * x.x, 0.125f * x.y);
      dst[2 * u + 1] = f2h2(0.125f * x.z, 0.125f * x.w);
    }
  }

  // Prologue: prefetch KV tile 0
  float4 kr[4], vr[4];
  #pragma unroll
  for (int u = 0; u < 4; u++) {
    kr[u] = *(const float4*)(kv_k + 4 * u);
    vr[u] = *(const float4*)(kv_v + 4 * u);
  }

  float o[8][4];
  #pragma unroll
  for (int ni = 0; ni < 8; ni++)
    #pragma unroll
    for (int r = 0; r < 4; r++) o[ni][r] = 0.0f;
  float mrow0 = -1e30f, mrow1 = -1e30f;
  float lrow0 = 0.0f, lrow1 = 0.0f;

  const int NT = LL / 64;
  for (int t = 0; t < NT; t++) {
    // Store K [tok][d halves] and V transposed [d][tok halves]
    {
      uint32_t* kd = &Ks[tok * HS + (d0 >> 1)];
      #pragma unroll
      for (int u = 0; u < 4; u++) {
        kd[2 * u + 0] = f2h2(kr[u].x, kr[u].y);
        kd[2 * u + 1] = f2h2(kr[u].z, kr[u].w);
        int dd = d0 + 4 * u;
        Vs_h[(dd + 0) * (2 * HS) + tok] = __float2half_rn(vr[u].x);
        Vs_h[(dd + 1) * (2 * HS) + tok] = __float2half_rn(vr[u].y);
        Vs_h[(dd + 2) * (2 * HS) + tok] = __float2half_rn(vr[u].z);
        Vs_h[(dd + 3) * (2 * HS) + tok] = __float2half_rn(vr[u].w);
      }
    }
    __syncthreads();

    // Prefetch next KV tile (drains behind mma work)
    if (t + 1 < NT) {
      const float* nk = kv_k + (size_t)(t + 1) * 64 * DD;
      const float* nv = kv_v + (size_t)(t + 1) * 64 * DD;
      #pragma unroll
      for (int u = 0; u < 4; u++) {
        kr[u] = *(const float4*)(nk + 4 * u);
        vr[u] = *(const float4*)(nv + 4 * u);
      }
    }

    // S = Q K^T  (4 k16 steps over d=64)
    float sacc[8][4];
    #pragma unroll
    for (int ni = 0; ni < 8; ni++)
      #pragma unroll
      for (int r = 0; r < 4; r++) sacc[ni][r] = 0.0f;

    #pragma unroll
    for (int ks = 0; ks < 4; ks++) {
      uint32_t a[4];
      ldsm_x4(a, qs_u + a_lnoff + ks * 32);
      #pragma unroll
      for (int ni = 0; ni < 8; ni += 2) {
        uint32_t bq[4];
        ldsm_x4(bq, ks_u + b_lnoff + (uint32_t)(ni * 8 * HS * 4) + ks * 32);
        mma_f16(sacc[ni], a, bq[0], bq[1]);
        mma_f16(sacc[ni + 1], a, bq[2], bq[3]);
      }
    }

    // Warp-local online softmax
    float mx0 = -1e30f, mx1 = -1e30f;
    #pragma unroll
    for (int ni = 0; ni < 8; ni++) {
      mx0 = fmaxf(mx0, fmaxf(sacc[ni][0], sacc[ni][1]));
      mx1 = fmaxf(mx1, fmaxf(sacc[ni][2], sacc[ni][3]));
    }
    mx0 = fmaxf(mx0, __shfl_xor_sync(0xffffffffu, mx0, 1));
    mx0 = fmaxf(mx0, __shfl_xor_sync(0xffffffffu, mx0, 2));
    mx1 = fmaxf(mx1, __shfl_xor_sync(0xffffffffu, mx1, 1));
    mx1 = fmaxf(mx1, __shfl_xor_sync(0xffffffffu, mx1, 2));

    float mn0 = fmaxf(mrow0, mx0);
    float mn1 = fmaxf(mrow1, mx1);
    float corr0 = __expf(mrow0 - mn0);
    float corr1 = __expf(mrow1 - mn1);
    mrow0 = mn0; mrow1 = mn1;

    float ls0 = 0.0f, ls1 = 0.0f;
    #pragma unroll
    for (int ni = 0; ni < 8; ni++) {
      float p00 = __expf(sacc[ni][0] - mn0);
      float p01 = __expf(sacc[ni][1] - mn0);
      float p10 = __expf(sacc[ni][2] - mn1);
      float p11 = __expf(sacc[ni][3] - mn1);
      ls0 += p00 + p01;
      ls1 += p10 + p11;
      // P halves: cols (ni*8+2tc, +1) -> word ni*4+tc
      Ps[(wrow + g) * HS + ni * 4 + tc] = f2h2(p00, p01);
      Ps[(wrow + g + 8) * HS + ni * 4 + tc] = f2h2(p10, p11);
    }
    ls0 += __shfl_xor_sync(0xffffffffu, ls0, 1);
    ls0 += __shfl_xor_sync(0xffffffffu, ls0, 2);
    ls1 += __shfl_xor_sync(0xffffffffu, ls1, 1);
    ls1 += __shfl_xor_sync(0xffffffffu, ls1, 2);
    lrow0 = lrow0 * corr0 + ls0;
    lrow1 = lrow1 * corr1 + ls1;

    #pragma unroll
    for (int ni = 0; ni < 8; ni++) {
      o[ni][0] *= corr0; o[ni][1] *= corr0;
      o[ni][2] *= corr1; o[ni][3] *= corr1;
    }
    __syncwarp();

    // O += P @ V  (4 k16 steps over kv=64)
    #pragma unroll
    for (int ks = 0; ks < 4; ks++) {
      uint32_t a[4];
      ldsm_x4(a, ps_u + a_lnoff + ks * 32);
      #pragma unroll
      for (int ni = 0; ni < 8; ni += 2) {
        uint32_t bv[4];
        ldsm_x4(bv, vs_u + b_lnoff + (uint32_t)(ni * 8 * HS * 4) + ks * 32);
        mma_f16(o[ni], a, bv[0], bv[1]);
        mma_f16(o[ni + 1], a, bv[2], bv[3]);
      }
    }
    __syncthreads();
  }

  // Normalize and store
  float inv0 = 1.0f / lrow0;
  float inv1 = 1.0f / lrow1;
  #pragma unroll
  for (int ni = 0; ni < 8; ni++) {
    int col = hoff + ni * 8 + 2 * tc;
    int row0 = qrow0 + wrow + g;
    *(float2*)&gctx[(size_t)row0 * DD + col] =
        make_float2(o[ni][0] * inv0, o[ni][1] * inv0);
    *(float2*)&gctx[(size_t)(row0 + 8) * DD + col] =
        make_float2(o[ni][2] * inv1, o[ni][3] * inv1);
  }
}

// ---------------------------------------------------------------------------
extern "C" void kernel_launch(void* const* d_in, const int* in_sizes, int n_in,
                              void* d_out, int out_size) {
  const float* query    = (const float*)d_in[0];
  const float* key      = (const float*)d_in[1];
  const float* value    = (const float*)d_in[2];
  const float* rot      = (const float*)d_in[3];
  const float* q_kernel = (const float*)d_in[4];
  const float* k_kernel = (const float*)d_in[5];
  const float* v_kernel = (const float*)d_in[6];
  const float* o_kernel = (const float*)d_in[7];
  float* out = (float*)d_out;

  float *pq, *pk, *pv, *pctx;
  cudaGetSymbolAddress((void**)&pq, g_q);
  cudaGetSymbolAddress((void**)&pk, g_k);
  cudaGetSymbolAddress((void**)&pv, g_v);
  cudaGetSymbolAddress((void**)&pctx, g_ctx);

  // QKV projections fused into one launch (grid.z selects A/B/C), fp16 mma
  gemm_f16_db<<<dim3(DD / 128, MROWS / 128, 3), 256>>>(
      query, key, value, q_kernel, k_kernel, v_kernel, pq, pk, pv,
      MROWS, DD, DD);

  // RoPE on q, k
  {
    int total = MROWS * HH * (ROT / 2);
    rope_kernel<<<(total + 255) / 256, 256>>>(pq, pk, rot);
  }

  // Flash attention (fp16 tensor cores + ldmatrix + KV register prefetch)
  cudaFuncSetAttribute(flash_attn_tc, cudaFuncAttributeMaxDynamicSharedMemorySize,
                       FA_SMEM_BYTES);
  flash_attn_tc<<<dim3(LL / 128, HH, BB), 256, FA_SMEM_BYTES>>>(pq, pk, pv, pctx);

  // Output projection (fp16 mma)
  gemm_f16_db<<<dim3(DD / 128, MROWS / 128, 1), 256>>>(
      pctx, pctx, pctx, o_kernel, o_kernel, o_kernel, out, out, out,
      MROWS, DD, DD);
}

// round 15
// speedup vs baseline: 4.0473x; 1.1410x over previous
#include <cuda_runtime.h>
#include <cuda_fp16.h>
#include <math.h>
#include <stdint.h>

// Problem constants
#define BB 2
#define LL 2048
#define DD 1024
#define HH 16
#define KK 64
#define ROT 32
#define MROWS (BB * LL)   // 4096

// Scratch (static device arrays: allocation-free)
__device__ float g_q[MROWS * DD];
__device__ float g_k[MROWS * DD];
__device__ float g_v[MROWS * DD];
__device__ float g_ctx[MROWS * DD];

__device__ __forceinline__ uint32_t f2h2(float lo, float hi) {
  __half2 h = __floats2half2_rn(lo, hi);
  return *reinterpret_cast<uint32_t*>(&h);
}

__device__ __forceinline__ void mma_f16(float c[4], const uint32_t a[4],
                                        uint32_t b0, uint32_t b1) {
  asm("mma.sync.aligned.m16n8k16.row.col.f32.f16.f16.f32 "
      "{%0,%1,%2,%3},{%4,%5,%6,%7},{%8,%9},{%0,%1,%2,%3};"
      : "+f"(c[0]), "+f"(c[1]), "+f"(c[2]), "+f"(c[3])
      : "r"(a[0]), "r"(a[1]), "r"(a[2]), "r"(a[3]), "r"(b0), "r"(b1));
}

__device__ __forceinline__ void ldsm_x4(uint32_t* r, uint32_t addr) {
  asm volatile("ldmatrix.sync.aligned.m8n8.x4.shared.b16 {%0,%1,%2,%3}, [%4];"
               : "=r"(r[0]), "=r"(r[1]), "=r"(r[2]), "=r"(r[3]) : "r"(addr));
}

__device__ __forceinline__ uint32_t s2u(const void* p) {
  return (uint32_t)__cvta_generic_to_shared(p);
}

// ---------------------------------------------------------------------------
// FP16 tensor-core GEMM, double-buffered, ldmatrix both operands.
// R15 change: A producer is float4-linear -> fully coalesced LDG (4 wf/instr
// instead of 32). smem layout and all consumer formulas unchanged from R13/14.
// ---------------------------------------------------------------------------
#define GSTR 24   // words per smem row (96 bytes)

__global__ __launch_bounds__(256, 2) void gemm_f16_db(
    const float* __restrict__ A0, const float* __restrict__ A1,
    const float* __restrict__ A2, const float* __restrict__ B0,
    const float* __restrict__ B1, const float* __restrict__ B2,
    float* __restrict__ C0, float* __restrict__ C1, float* __restrict__ C2,
    int M, int N, int Kd) {
  __shared__ uint32_t As[2][128 * GSTR];
  __shared__ uint32_t Bs[2][128 * GSTR];

  const int z = blockIdx.z;
  const float* A = (z == 0) ? A0 : (z == 1) ? A1 : A2;
  const float* B = (z == 0) ? B0 : (z == 1) ? B1 : B2;
  float* C = (z == 0) ? C0 : (z == 1) ? C1 : C2;

  const int tid = threadIdx.x;
  const int warp = tid >> 5, lane = tid & 31;
  const int g = lane >> 2, tc = lane & 3;
  const int wm = warp & 3, wn = warp >> 2;
  const int m_base = wm * 32;
  const int n_base = wn * 64;
  const int crow = blockIdx.y * 128;
  const int ccol = blockIdx.x * 128;

  // A producer (coalesced): f4idx = tid + 256j -> row = (tid>>3)+32j, kc4=tid&7
  const int ar = tid >> 3;           // base row 0..31
  const int akc = tid & 7;           // float4 index within row (k = 4*akc)
  const int apsw = (ar >> 2) & 3;    // swizzle, invariant in j
  const uint32_t aw = 4 * ((akc >> 1) ^ apsw) + 2 * (akc & 1);
  uint32_t a_sts[4];
  const float* ApGj[4];
  #pragma unroll
  for (int j = 0; j < 4; j++) {
    a_sts[j] = (uint32_t)(ar + 32 * j) * GSTR + aw;
    ApGj[j] = A + (size_t)(crow + ar + 32 * j) * Kd + 4 * akc;
  }

  // B producer (unchanged; coalesced)
  const int pr = tid & 127;
  const int pkh = tid >> 7;
  const int psw = (pr >> 2) & 3;
  const uint32_t bw0 = pr * GSTR + 4 * ((2 * pkh) ^ psw);
  const uint32_t bw1 = pr * GSTR + 4 * ((2 * pkh + 1) ^ psw);
  const float* BpG = B + (size_t)(16 * pkh) * N + ccol + pr;

  // Consumers (unchanged)
  const uint32_t a_row_b = (uint32_t)(m_base + (lane & 15)) * 96;
  const int a_sw = ((lane & 15) >> 2) & 3;
  const int a_kb = lane >> 4;
  const uint32_t b_row_b =
      (uint32_t)(n_base + 8 * (lane >> 4) + (lane & 7)) * 96;
  const int b_kb = (lane >> 3) & 1;
  const int b_sw = (2 * (lane >> 4) + ((lane & 7) >> 2)) & 3;

  float acc[2][8][4];
  #pragma unroll
  for (int mi = 0; mi < 2; mi++)
    #pragma unroll
    for (int ni = 0; ni < 8; ni++)
      #pragma unroll
      for (int r = 0; r < 4; r++) acc[mi][ni][r] = 0.0f;

  // Prologue: tile 0 -> buffer 0
  float4 af[4];
  float bf[16];
  #pragma unroll
  for (int j = 0; j < 4; j++) af[j] = *(const float4*)ApGj[j];
  #pragma unroll
  for (int j = 0; j < 16; j++) bf[j] = BpG[(size_t)j * N];
  BpG += (size_t)32 * N;
  {
    uint32_t* as = As[0];
    #pragma unroll
    for (int j = 0; j < 4; j++)
      *(uint2*)&as[a_sts[j]] =
          make_uint2(f2h2(af[j].x, af[j].y), f2h2(af[j].z, af[j].w));
    uint32_t* bs = Bs[0];
    *(uint4*)&bs[bw0] = make_uint4(f2h2(bf[0], bf[1]), f2h2(bf[2], bf[3]),
                                   f2h2(bf[4], bf[5]), f2h2(bf[6], bf[7]));
    *(uint4*)&bs[bw1] = make_uint4(f2h2(bf[8], bf[9]), f2h2(bf[10], bf[11]),
                                   f2h2(bf[12], bf[13]), f2h2(bf[14], bf[15]));
  }
  __syncthreads();

  const uint32_t as_u[2] = {s2u(As[0]), s2u(As[1])};
  const uint32_t bs_u[2] = {s2u(Bs[0]), s2u(Bs[1])};

  int buf = 0;
  const int iters = Kd / 32;
  for (int it = 0; it < iters; it++) {
    const bool last = (it == iters - 1);
    if (!last) {
      #pragma unroll
      for (int j = 0; j < 4; j++)
        af[j] = *(const float4*)(ApGj[j] + (size_t)(it + 1) * 32);
      #pragma unroll
      for (int j = 0; j < 16; j++) bf[j] = BpG[(size_t)j * N];
      BpG += (size_t)32 * N;
    }

    const uint32_t au = as_u[buf];
    const uint32_t bu = bs_u[buf];
    #pragma unroll
    for (int s = 0; s < 2; s++) {
      uint32_t afr[2][4];
      const uint32_t a_k = 16u * (uint32_t)((2 * s + a_kb) ^ a_sw);
      ldsm_x4(afr[0], au + a_row_b + a_k);
      ldsm_x4(afr[1], au + a_row_b + 1536 + a_k);
      const uint32_t b_k = 16u * (uint32_t)((2 * s + b_kb) ^ b_sw);
      #pragma unroll
      for (int p = 0; p < 4; p++) {
        uint32_t bq[4];
        ldsm_x4(bq, bu + b_row_b + (uint32_t)(p * 1536) + b_k);
        mma_f16(acc[0][2 * p],     afr[0], bq[0], bq[1]);
        mma_f16(acc[0][2 * p + 1], afr[0], bq[2], bq[3]);
        mma_f16(acc[1][2 * p],     afr[1], bq[0], bq[1]);
        mma_f16(acc[1][2 * p + 1], afr[1], bq[2], bq[3]);
      }
    }

    if (!last) {
      uint32_t* as = As[buf ^ 1];
      #pragma unroll
      for (int j = 0; j < 4; j++)
        *(uint2*)&as[a_sts[j]] =
            make_uint2(f2h2(af[j].x, af[j].y), f2h2(af[j].z, af[j].w));
      uint32_t* bs = Bs[buf ^ 1];
      *(uint4*)&bs[bw0] = make_uint4(f2h2(bf[0], bf[1]), f2h2(bf[2], bf[3]),
                                     f2h2(bf[4], bf[5]), f2h2(bf[6], bf[7]));
      *(uint4*)&bs[bw1] = make_uint4(f2h2(bf[8], bf[9]), f2h2(bf[10], bf[11]),
                                     f2h2(bf[12], bf[13]), f2h2(bf[14], bf[15]));
      __syncthreads();
      buf ^= 1;
    }
  }

  #pragma unroll
  for (int mi = 0; mi < 2; mi++) {
    #pragma unroll
    for (int ni = 0; ni < 8; ni++) {
      int row = crow + m_base + mi * 16 + g;
      int col = ccol + n_base + ni * 8 + 2 * tc;
      *(float2*)&C[(size_t)row * N + col] =
          make_float2(acc[mi][ni][0], acc[mi][ni][1]);
      *(float2*)&C[(size_t)(row + 8) * N + col] =
          make_float2(acc[mi][ni][2], acc[mi][ni][3]);
    }
  }
}

// ---------------------------------------------------------------------------
// RoPE applied in-place to q and k (first ROT dims of each head)
// ---------------------------------------------------------------------------
__global__ void rope_kernel(float* __restrict__ q, float* __restrict__ k,
                            const float* __restrict__ rot) {
  int idx = blockIdx.x * 256 + threadIdx.x;
  const int total = MROWS * HH * (ROT / 2);
  if (idx >= total) return;
  int i = idx & 15;
  int h = (idx >> 4) & 15;
  int row = idx >> 8;
  int l = row & (LL - 1);

  float f0 = rot[l * ROT + 2 * i];
  float f1 = rot[l * ROT + 2 * i + 1];
  float s0, c0, s1, c1;
  sincosf(f0, &s0, &c0);
  sincosf(f1, &s1, &c1);

  int base = row * DD + h * KK + 2 * i;
  float2 tq = *(float2*)&q[base];
  float2 tk = *(float2*)&k[base];
  float2 oq, ok;
  oq.x = tq.x * c0 - tq.y * s0;
  oq.y = tq.y * c1 + tq.x * s1;
  ok.x = tk.x * c0 - tk.y * s0;
  ok.y = tk.y * c1 + tk.x * s1;
  *(float2*)&q[base] = oq;
  *(float2*)&k[base] = ok;
}

// ---------------------------------------------------------------------------
// Flash attention, FP16 tensor cores (m16n8k16) + ldmatrix + reg-prefetch KV.
// (Unchanged from R14 passing version, 565us.)
// ---------------------------------------------------------------------------
#define HS 36
#define FA_SMEM_WORDS ((128 + 64 + 64 + 128) * HS)
#define FA_SMEM_BYTES (FA_SMEM_WORDS * 4)

__global__ __launch_bounds__(256) void flash_attn_tc(
    const float* __restrict__ gq, const float* __restrict__ gk,
    const float* __restrict__ gv, float* __restrict__ gctx) {
  extern __shared__ uint32_t usm[];
  uint32_t* Qs = usm;               // [128][HS]
  uint32_t* Ks = Qs + 128 * HS;     // [64][HS]
  uint32_t* Vs = Ks + 64 * HS;      // [64][HS]
  uint32_t* Ps = Vs + 64 * HS;      // [128][HS]
  __half* Vs_h = reinterpret_cast<__half*>(Vs);

  const int tid = threadIdx.x;
  const int warp = tid >> 5, lane = tid & 31;
  const int g = lane >> 2, tc = lane & 3;
  const int qt = blockIdx.x, h = blockIdx.y, b = blockIdx.z;
  const int qrow0 = b * LL + qt * 128;
  const int hoff = h * KK;
  const int wrow = warp * 16;

  const uint32_t a_lnoff = ((wrow + (lane & 15)) * HS + 4 * (lane >> 4)) * 4;
  const uint32_t b_lnoff =
      ((8 * (lane >> 4) + (lane & 7)) * HS + 4 * ((lane >> 3) & 1)) * 4;
  const uint32_t qs_u = s2u(Qs), ks_u = s2u(Ks), vs_u = s2u(Vs), ps_u = s2u(Ps);

  const int tok = tid >> 2;
  const int d0 = (tid & 3) * 16;
  const float* kv_k = gk + (size_t)(b * LL + tok) * DD + hoff + d0;
  const float* kv_v = gv + (size_t)(b * LL + tok) * DD + hoff + d0;

  {
    int r = tid >> 1;
    int dq = (tid & 1) * 32;
    const float* src = gq + (size_t)(qrow0 + r) * DD + hoff + dq;
    uint32_t* dst = &Qs[r * HS + (dq >> 1)];
    #pragma unroll
    for (int u = 0; u < 8; u++) {
      float4 x = *(const float4*)(src + 4 * u);
      dst[2 * u + 0] = f2h2(0.125f * x.x, 0.125f * x.y);
      dst[2 * u + 1] = f2h2(0.125f * x.z, 0.125f * x.w);
    }
  }

  float4 kr[4], vr[4];
  #pragma unroll
  for (int u = 0; u < 4; u++) {
    kr[u] = *(const float4*)(kv_k + 4 * u);
    vr[u] = *(const float4*)(kv_v + 4 * u);
  }

  float o[8][4];
  #pragma unroll
  for (int ni = 0; ni < 8; ni++)
    #pragma unroll
    for (int r = 0; r < 4; r++) o[ni][r] = 0.0f;
  float mrow0 = -1e30f, mrow1 = -1e30f;
  float lrow0 = 0.0f, lrow1 = 0.0f;

  const int NT = LL / 64;
  for (int t = 0; t < NT; t++) {
    {
      uint32_t* kd = &Ks[tok * HS + (d0 >> 1)];
      #pragma unroll
      for (int u = 0; u < 4; u++) {
        kd[2 * u + 0] = f2h2(kr[u].x, kr[u].y);
        kd[2 * u + 1] = f2h2(kr[u].z, kr[u].w);
        int dd = d0 + 4 * u;
        Vs_h[(dd + 0) * (2 * HS) + tok] = __float2half_rn(vr[u].x);
        Vs_h[(dd + 1) * (2 * HS) + tok] = __float2half_rn(vr[u].y);
        Vs_h[(dd + 2) * (2 * HS) + tok] = __float2half_rn(vr[u].z);
        Vs_h[(dd + 3) * (2 * HS) + tok] = __float2half_rn(vr[u].w);
      }
    }
    __syncthreads();

    if (t + 1 < NT) {
      const float* nk = kv_k + (size_t)(t + 1) * 64 * DD;
      const float* nv = kv_v + (size_t)(t + 1) * 64 * DD;
      #pragma unroll
      for (int u = 0; u < 4; u++) {
        kr[u] = *(const float4*)(nk + 4 * u);
        vr[u] = *(const float4*)(nv + 4 * u);
      }
    }

    float sacc[8][4];
    #pragma unroll
    for (int ni = 0; ni < 8; ni++)
      #pragma unroll
      for (int r = 0; r < 4; r++) sacc[ni][r] = 0.0f;

    #pragma unroll
    for (int ks = 0; ks < 4; ks++) {
      uint32_t a[4];
      ldsm_x4(a, qs_u + a_lnoff + ks * 32);
      #pragma unroll
      for (int ni = 0; ni < 8; ni += 2) {
        uint32_t bq[4];
        ldsm_x4(bq, ks_u + b_lnoff + (uint32_t)(ni * 8 * HS * 4) + ks * 32);
        mma_f16(sacc[ni], a, bq[0], bq[1]);
        mma_f16(sacc[ni + 1], a, bq[2], bq[3]);
      }
    }

    float mx0 = -1e30f, mx1 = -1e30f;
    #pragma unroll
    for (int ni = 0; ni < 8; ni++) {
      mx0 = fmaxf(mx0, fmaxf(sacc[ni][0], sacc[ni][1]));
      mx1 = fmaxf(mx1, fmaxf(sacc[ni][2], sacc[ni][3]));
    }
    mx0 = fmaxf(mx0, __shfl_xor_sync(0xffffffffu, mx0, 1));
    mx0 = fmaxf(mx0, __shfl_xor_sync(0xffffffffu, mx0, 2));
    mx1 = fmaxf(mx1, __shfl_xor_sync(0xffffffffu, mx1, 1));
    mx1 = fmaxf(mx1, __shfl_xor_sync(0xffffffffu, mx1, 2));

    float mn0 = fmaxf(mrow0, mx0);
    float mn1 = fmaxf(mrow1, mx1);
    float corr0 = __expf(mrow0 - mn0);
    float corr1 = __expf(mrow1 - mn1);
    mrow0 = mn0; mrow1 = mn1;

    float ls0 = 0.0f, ls1 = 0.0f;
    #pragma unroll
    for (int ni = 0; ni < 8; ni++) {
      float p00 = __expf(sacc[ni][0] - mn0);
      float p01 = __expf(sacc[ni][1] - mn0);
      float p10 = __expf(sacc[ni][2] - mn1);
      float p11 = __expf(sacc[ni][3] - mn1);
      ls0 += p00 + p01;
      ls1 += p10 + p11;
      Ps[(wrow + g) * HS + ni * 4 + tc] = f2h2(p00, p01);
      Ps[(wrow + g + 8) * HS + ni * 4 + tc] = f2h2(p10, p11);
    }
    ls0 += __shfl_xor_sync(0xffffffffu, ls0, 1);
    ls0 += __shfl_xor_sync(0xffffffffu, ls0, 2);
    ls1 += __shfl_xor_sync(0xffffffffu, ls1, 1);
    ls1 += __shfl_xor_sync(0xffffffffu, ls1, 2);
    lrow0 = lrow0 * corr0 + ls0;
    lrow1 = lrow1 * corr1 + ls1;

    #pragma unroll
    for (int ni = 0; ni < 8; ni++) {
      o[ni][0] *= corr0; o[ni][1] *= corr0;
      o[ni][2] *= corr1; o[ni][3] *= corr1;
    }
    __syncwarp();

    #pragma unroll
    for (int ks = 0; ks < 4; ks++) {
      uint32_t a[4];
      ldsm_x4(a, ps_u + a_lnoff + ks * 32);
      #pragma unroll
      for (int ni = 0; ni < 8; ni += 2) {
        uint32_t bv[4];
        ldsm_x4(bv, vs_u + b_lnoff + (uint32_t)(ni * 8 * HS * 4) + ks * 32);
        mma_f16(o[ni], a, bv[0], bv[1]);
        mma_f16(o[ni + 1], a, bv[2], bv[3]);
      }
    }
    __syncthreads();
  }

  float inv0 = 1.0f / lrow0;
  float inv1 = 1.0f / lrow1;
  #pragma unroll
  for (int ni = 0; ni < 8; ni++) {
    int col = hoff + ni * 8 + 2 * tc;
    int row0 = qrow0 + wrow + g;
    *(float2*)&gctx[(size_t)row0 * DD + col] =
        make_float2(o[ni][0] * inv0, o[ni][1] * inv0);
    *(float2*)&gctx[(size_t)(row0 + 8) * DD + col] =
        make_float2(o[ni][2] * inv1, o[ni][3] * inv1);
  }
}

// ---------------------------------------------------------------------------
extern "C" void kernel_launch(void* const* d_in, const int* in_sizes, int n_in,
                              void* d_out, int out_size) {
  const float* query    = (const float*)d_in[0];
  const float* key      = (const float*)d_in[1];
  const float* value    = (const float*)d_in[2];
  const float* rot      = (const float*)d_in[3];
  const float* q_kernel = (const float*)d_in[4];
  const float* k_kernel = (const float*)d_in[5];
  const float* v_kernel = (const float*)d_in[6];
  const float* o_kernel = (const float*)d_in[7];
  float* out = (float*)d_out;

  float *pq, *pk, *pv, *pctx;
  cudaGetSymbolAddress((void**)&pq, g_q);
  cudaGetSymbolAddress((void**)&pk, g_k);
  cudaGetSymbolAddress((void**)&pv, g_v);
  cudaGetSymbolAddress((void**)&pctx, g_ctx);

  // QKV projections fused into one launch (grid.z selects A/B/C), fp16 mma
  gemm_f16_db<<<dim3(DD / 128, MROWS / 128, 3), 256>>>(
      query, key, value, q_kernel, k_kernel, v_kernel, pq, pk, pv,
      MROWS, DD, DD);

  // RoPE on q, k
  {
    int total = MROWS * HH * (ROT / 2);
    rope_kernel<<<(total + 255) / 256, 256>>>(pq, pk, rot);
  }

  // Flash attention (fp16 tensor cores + ldmatrix + KV register prefetch)
  cudaFuncSetAttribute(flash_attn_tc, cudaFuncAttributeMaxDynamicSharedMemorySize,
                       FA_SMEM_BYTES);
  flash_attn_tc<<<dim3(LL / 128, HH, BB), 256, FA_SMEM_BYTES>>>(pq, pk, pv, pctx);

  // Output projection (fp16 mma)
  gemm_f16_db<<<dim3(DD / 128, MROWS / 128, 1), 256>>>(
      pctx, pctx, pctx, o_kernel, o_kernel, o_kernel, out, out, out,
      MROWS, DD, DD);
}